// round 4
// baseline (speedup 1.0000x reference)
#include <cuda_runtime.h>
#include <cstdint>

#define B_      8
#define Q_      2048
#define DIM_    256
#define NH      8
#define HD      32
#define DFF     1024
#define LEN_IN_ 13294
#define BQ      (B_*Q_)
#define MV      (B_*LEN_IN_)   // 106352 rows of the value GEMM

// ---------------- scratch (static device arrays; no allocation) ----------------
__device__ float g_qp[BQ*DIM_];            // LN1(input)+pos
__device__ float g_value[MV*DIM_];         // source @ Wv + bv   (109 MB)
__device__ float g_off[BQ*DIM_];           // offset projections
__device__ float g_attn[BQ*128];           // attn logits (softmax fused into sampler)
__device__ float g_attnout[BQ*DIM_];       // sampled attention output
__device__ float g_x[BQ*DIM_];             // residual 1
__device__ float g_y[BQ*DIM_];             // LN2 output
__device__ float g_ffn[BQ*DFF];            // FFN hidden

// ---------------- LayerNorm (+ optional additive term) ----------------
__global__ __launch_bounds__(256) void ln_kernel(
    const float* __restrict__ x, const float* __restrict__ g,
    const float* __restrict__ b, const float* __restrict__ addend,
    float* __restrict__ out)
{
    __shared__ float sbuf[8];
    const int row = blockIdx.x;
    const int t = threadIdx.x;
    const float v = x[(size_t)row*DIM_ + t];

    float s = v;
    #pragma unroll
    for (int o = 16; o; o >>= 1) s += __shfl_xor_sync(0xffffffffu, s, o);
    if ((t & 31) == 0) sbuf[t >> 5] = s;
    __syncthreads();
    float mean = 0.f;
    #pragma unroll
    for (int i = 0; i < 8; i++) mean += sbuf[i];
    mean *= (1.f/256.f);

    const float d = v - mean;
    float s2 = d*d;
    #pragma unroll
    for (int o = 16; o; o >>= 1) s2 += __shfl_xor_sync(0xffffffffu, s2, o);
    __syncthreads();
    if ((t & 31) == 0) sbuf[t >> 5] = s2;
    __syncthreads();
    float var = 0.f;
    #pragma unroll
    for (int i = 0; i < 8; i++) var += sbuf[i];
    var *= (1.f/256.f);

    float r = d * rsqrtf(var + 1e-5f) * g[t] + b[t];
    if (addend) r += addend[(size_t)row*DIM_ + t];
    out[(size_t)row*DIM_ + t] = r;
}

// ---------------- tf32 helpers ----------------
__device__ __forceinline__ uint32_t f2tf32(float f) {
    uint32_t u;
    asm("cvt.rna.tf32.f32 %0, %1;" : "=r"(u) : "f"(f));
    return u;
}

__device__ __forceinline__ void mma_tf32(float c[4], const uint32_t a[4], const uint32_t b[2]) {
    asm("mma.sync.aligned.m16n8k8.row.col.f32.tf32.tf32.f32 "
        "{%0,%1,%2,%3}, {%4,%5,%6,%7}, {%8,%9}, {%0,%1,%2,%3};"
        : "+f"(c[0]), "+f"(c[1]), "+f"(c[2]), "+f"(c[3])
        : "r"(a[0]), "r"(a[1]), "r"(a[2]), "r"(a[3]), "r"(b[0]), "r"(b[1]));
}

__device__ __forceinline__ void cp_async16(void* smem_dst, const void* gsrc) {
    uint32_t s = (uint32_t)__cvta_generic_to_shared(smem_dst);
    asm volatile("cp.async.cg.shared.global [%0], [%1], 16;" :: "r"(s), "l"(gsrc));
}
__device__ __forceinline__ void cp_commit() { asm volatile("cp.async.commit_group;"); }
__device__ __forceinline__ void cp_wait0()  { asm volatile("cp.async.wait_group 0;"); }

// ---------------- TF32 tensor-core GEMM (2-stage, high-occupancy) ----------------
// C = act(A@B + bias) [+resid] [mask rows]
// A: [M,K] row-major, B: [K,N] row-major. N % 128 == 0, K % 32 == 0. M guarded.
// CTA tile 64x128, K-tile 32, 4 warps (1 M x 4 N), warp tile 64x32.
// 3 CTAs/SM resident (12 warps) so syncs/memory waits overlap across CTAs.
#define A_STAGE 2048                   // uint32 per stage (4 kk * 4 mrow * 128)
#define B_STR   136                    // padded row stride (floats)
#define B_STAGE (32*B_STR)             // floats per stage
#define GEMM_SMEM_BYTES ((2*A_STAGE + 2*B_STAGE) * 4)

__global__ __launch_bounds__(128, 3) void gemm_tc(
    const float* __restrict__ A, const float* __restrict__ Bm,
    const float* __restrict__ bias, const float* __restrict__ resid,
    const uint8_t* __restrict__ mask, float* __restrict__ C,
    int M, int N, int K, int relu)
{
    extern __shared__ float dynsmem[];
    uint32_t* AsF = (uint32_t*)dynsmem;          // [2][A_STAGE]
    float*    BsS = dynsmem + 2*A_STAGE;         // [2][32][B_STR]

    const int tid   = threadIdx.x;
    const int warpN = tid >> 5;      // 4 warps over N
    const int lane  = tid & 31;
    const int gid   = lane >> 2;     // 0..7
    const int tig   = lane & 3;      // 0..3
    const int row0  = blockIdx.y * 64;
    const int col0  = blockIdx.x * 128;

    // A global-load slot: 16 floats per thread (row a_row, k in [a_col, a_col+16))
    const int a_row = tid >> 1;            // 0..63
    const int a_col = (tid & 1) << 4;      // 0 or 16
    const bool avalid = (row0 + a_row) < M;
    const float* aptr = A + (size_t)(row0 + a_row) * K + a_col;

    // A fragment-permute destination pieces:
    // idx = ((kk*4 + mrow)<<7) + ((row&7)*4 + (k&3))*4 + ((k>>2)&1)*2 + ((row>>3)&1)
    const int a_mrow   = a_row >> 4;
    const int a_hm     = (a_row >> 3) & 1;
    const int a_within = (a_row & 7) << 2;

    float acc[4][4][4];
    #pragma unroll
    for (int i = 0; i < 4; i++)
        #pragma unroll
        for (int j = 0; j < 4; j++)
            #pragma unroll
            for (int r = 0; r < 4; r++) acc[i][j][r] = 0.f;

    const int nkt = K >> 5;
    float4 ra[4];

    // ---- prologue: A(0) -> regs, B(0) -> cp.async stage 0 ----
    #pragma unroll
    for (int i = 0; i < 4; i++)
        ra[i] = avalid ? *(const float4*)(aptr + i*4) : make_float4(0.f,0.f,0.f,0.f);
    #pragma unroll
    for (int i = 0; i < 8; i++) {
        const int chunk = i*128 + tid;
        const int br = chunk >> 5;
        const int bn = (chunk & 31) << 2;
        cp_async16(&BsS[br*B_STR + bn], Bm + (size_t)br*N + col0 + bn);
    }
    cp_commit();

    // STS A(0) into stage 0 (fragment-permuted, tf32-rounded)
    {
        uint32_t* dst = AsF;
        #pragma unroll
        for (int i = 0; i < 4; i++) {
            float v[4] = {ra[i].x, ra[i].y, ra[i].z, ra[i].w};
            #pragma unroll
            for (int j = 0; j < 4; j++) {
                const int k  = a_col + i*4 + j;
                const int kk = k >> 3;
                const int idx = ((kk*4 + a_mrow) << 7) + ((a_within + (k & 3)) << 2)
                              + (((k >> 2) & 1) << 1) + a_hm;
                dst[idx] = f2tf32(v[j]);
            }
        }
    }

    for (int t = 0; t < nkt; t++) {
        const int p = t & 1;
        cp_wait0();
        __syncthreads();

        const bool more = (t + 1) < nkt;
        if (more) {
            const int k0n = (t + 1) << 5;
            #pragma unroll
            for (int i = 0; i < 4; i++)
                ra[i] = avalid ? *(const float4*)(aptr + k0n + i*4)
                               : make_float4(0.f,0.f,0.f,0.f);
            float* bdst = BsS + (p ^ 1) * B_STAGE;
            #pragma unroll
            for (int i = 0; i < 8; i++) {
                const int chunk = i*128 + tid;
                const int br = chunk >> 5;
                const int bn = (chunk & 31) << 2;
                cp_async16(&bdst[br*B_STR + bn], Bm + (size_t)(k0n + br)*N + col0 + bn);
            }
            cp_commit();
        }

        // ---- compute stage p ----
        const uint32_t* ab = AsF + p * A_STAGE;
        const float*    bb = BsS + p * B_STAGE;
        #pragma unroll
        for (int kk = 0; kk < 4; kk++) {
            uint32_t af[4][4];
            #pragma unroll
            for (int mt = 0; mt < 4; mt++) {
                const uint4 v = *(const uint4*)&ab[((kk*4 + mt) << 7) + (lane << 2)];
                af[mt][0] = v.x; af[mt][1] = v.y; af[mt][2] = v.z; af[mt][3] = v.w;
            }
            uint32_t bf[4][2];
            #pragma unroll
            for (int nt = 0; nt < 4; nt++) {
                const int c = warpN*32 + nt*8 + gid;
                bf[nt][0] = __float_as_uint(bb[(kk*8 + tig    )*B_STR + c]);
                bf[nt][1] = __float_as_uint(bb[(kk*8 + tig + 4)*B_STR + c]);
            }
            #pragma unroll
            for (int mt = 0; mt < 4; mt++)
                #pragma unroll
                for (int nt = 0; nt < 4; nt++)
                    mma_tf32(acc[mt][nt], af[mt], bf[nt]);
        }

        // ---- STS A(t+1) into other stage ----
        if (more) {
            uint32_t* dst = AsF + (p ^ 1) * A_STAGE;
            #pragma unroll
            for (int i = 0; i < 4; i++) {
                float v[4] = {ra[i].x, ra[i].y, ra[i].z, ra[i].w};
                #pragma unroll
                for (int j = 0; j < 4; j++) {
                    const int k  = a_col + i*4 + j;
                    const int kk = k >> 3;
                    const int idx = ((kk*4 + a_mrow) << 7) + ((a_within + (k & 3)) << 2)
                                  + (((k >> 2) & 1) << 1) + a_hm;
                    dst[idx] = f2tf32(v[j]);
                }
            }
        }
    }

    // ---- epilogue ----
    #pragma unroll
    for (int mt = 0; mt < 4; mt++) {
        #pragma unroll
        for (int half = 0; half < 2; half++) {
            const int r = row0 + mt*16 + gid + half*8;
            if (r >= M) continue;
            const float mz = (mask && mask[r]) ? 0.f : 1.f;
            #pragma unroll
            for (int nt = 0; nt < 4; nt++) {
                const int c = col0 + warpN*32 + nt*8 + 2*tig;
                float v0 = acc[mt][nt][half*2 + 0] + bias[c + 0];
                float v1 = acc[mt][nt][half*2 + 1] + bias[c + 1];
                if (relu) { v0 = fmaxf(v0, 0.f); v1 = fmaxf(v1, 0.f); }
                if (resid) {
                    const float* rp = resid + (size_t)r*N + c;
                    v0 += rp[0]; v1 += rp[1];
                }
                float2 vv = make_float2(v0*mz, v1*mz);
                *(float2*)(C + (size_t)r*N + c) = vv;
            }
        }
    }
}

// ---------------- fused loc + softmax + MS-deformable bilinear sampling ----------------
// block = one (b,q); warp = head; lane = head_dim channel.
__global__ __launch_bounds__(256) void sample_kernel(
    const float* __restrict__ value, const float* __restrict__ off,
    const float* __restrict__ attnlog, const float* __restrict__ ref,
    float* __restrict__ out_loc, float* __restrict__ out)
{
    __shared__ float s_loc[256];
    __shared__ float s_attn[128];

    const int bq   = blockIdx.x;
    const int tid  = threadIdx.x;
    const int h    = tid >> 5;
    const int lane = tid & 31;
    const int b    = bq >> 11;           // / Q_

    // loc = ref + off/normalizer (also stream to output)
    {
        const int c = tid & 1;
        const int l = (tid >> 3) & 3;
        const float nd[4] = {100.f, 50.f, 25.f, 13.f};
        const float v = ref[((size_t)bq*4 + l)*2 + c]
                      + off[(size_t)bq*256 + tid] / nd[l];
        s_loc[tid] = v;
        out_loc[(size_t)bq*256 + tid] = v;
    }
    // softmax over 16 points per head (16-lane segments of warps 0..3)
    if (tid < 128) {
        const float logit = attnlog[(size_t)bq*128 + tid];
        float m = logit;
        #pragma unroll
        for (int o = 8; o; o >>= 1) m = fmaxf(m, __shfl_xor_sync(0xffffffffu, m, o, 16));
        const float e = __expf(logit - m);
        float s = e;
        #pragma unroll
        for (int o = 8; o; o >>= 1) s += __shfl_xor_sync(0xffffffffu, s, o, 16);
        s_attn[tid] = e / s;
    }
    __syncthreads();

    const float* locp = s_loc  + h*32;
    const float* ap   = s_attn + h*16;

    constexpr int LH[4] = {100, 50, 25, 13};
    constexpr int LS[4] = {0, 10000, 12500, 13125};

    float acc = 0.f;
    #pragma unroll
    for (int l = 0; l < 4; l++) {
        const int Hh = LH[l], Ww = LH[l];
        const float* vb = value + ((size_t)b*LEN_IN_ + LS[l])*DIM_ + h*32 + lane;
        #pragma unroll
        for (int p = 0; p < 4; p++) {
            const float lx = locp[(l*4 + p)*2 + 0];
            const float ly = locp[(l*4 + p)*2 + 1];
            const float a  = ap[l*4 + p];
            const float x = lx * (float)Ww - 0.5f;
            const float y = ly * (float)Hh - 0.5f;
            const float x0f = floorf(x), y0f = floorf(y);
            const float wx = x - x0f, wy = y - y0f;
            const int x0 = (int)x0f, y0 = (int)y0f;
            const int x1 = x0 + 1,  y1 = y0 + 1;

            const float vx0 = (x0 >= 0 && x0 < Ww) ? 1.f : 0.f;
            const float vx1 = (x1 >= 0 && x1 < Ww) ? 1.f : 0.f;
            const float vy0 = (y0 >= 0 && y0 < Hh) ? 1.f : 0.f;
            const float vy1 = (y1 >= 0 && y1 < Hh) ? 1.f : 0.f;
            const int cx0 = min(max(x0, 0), Ww-1);
            const int cx1 = min(max(x1, 0), Ww-1);
            const int cy0 = min(max(y0, 0), Hh-1);
            const int cy1 = min(max(y1, 0), Hh-1);

            const float g00 = vb[(size_t)(cy0*Ww + cx0)*DIM_] * (vx0*vy0);
            const float g01 = vb[(size_t)(cy0*Ww + cx1)*DIM_] * (vx1*vy0);
            const float g10 = vb[(size_t)(cy1*Ww + cx0)*DIM_] * (vx0*vy1);
            const float g11 = vb[(size_t)(cy1*Ww + cx1)*DIM_] * (vx1*vy1);

            const float top = g00*(1.f-wx) + g01*wx;
            const float bot = g10*(1.f-wx) + g11*wx;
            acc += a * (top*(1.f-wy) + bot*wy);
        }
    }
    out[(size_t)bq*256 + h*32 + lane] = acc;
}

// ---------------- launch ----------------
extern "C" void kernel_launch(void* const* d_in, const int* in_sizes, int n_in,
                              void* d_out, int out_size)
{
    const float*   input  = (const float*)d_in[0];
    const float*   pos    = (const float*)d_in[1];
    const float*   refp   = (const float*)d_in[2];
    const float*   source = (const float*)d_in[3];
    // d_in[4] source_shape (int64), d_in[5] level_start (int64): compile-time constants
    const uint8_t* mask   = (const uint8_t*)d_in[6];
    const float*   ln1_g  = (const float*)d_in[7];
    const float*   ln1_b  = (const float*)d_in[8];
    const float*   ln2_g  = (const float*)d_in[9];
    const float*   ln2_b  = (const float*)d_in[10];
    const float*   Wv     = (const float*)d_in[11];
    const float*   bv     = (const float*)d_in[12];
    const float*   Woff   = (const float*)d_in[13];
    const float*   boff   = (const float*)d_in[14];
    const float*   Wattn  = (const float*)d_in[15];
    const float*   battn  = (const float*)d_in[16];
    const float*   Wout   = (const float*)d_in[17];
    const float*   bout   = (const float*)d_in[18];
    const float*   W1     = (const float*)d_in[19];
    const float*   b1     = (const float*)d_in[20];
    const float*   W2     = (const float*)d_in[21];
    const float*   b2     = (const float*)d_in[22];

    float* out_x   = (float*)d_out;
    float* out_loc = (float*)d_out + (size_t)BQ*DIM_;

    float *qp, *value, *off, *attn, *attnout, *xb, *yb, *ffn;
    cudaGetSymbolAddress((void**)&qp,      g_qp);
    cudaGetSymbolAddress((void**)&value,   g_value);
    cudaGetSymbolAddress((void**)&off,     g_off);
    cudaGetSymbolAddress((void**)&attn,    g_attn);
    cudaGetSymbolAddress((void**)&attnout, g_attnout);
    cudaGetSymbolAddress((void**)&xb,      g_x);
    cudaGetSymbolAddress((void**)&yb,      g_y);
    cudaGetSymbolAddress((void**)&ffn,     g_ffn);

    cudaFuncSetAttribute(gemm_tc, cudaFuncAttributeMaxDynamicSharedMemorySize,
                         GEMM_SMEM_BYTES);

    // 1) qp = LN1(input) + pos
    ln_kernel<<<BQ, 256>>>(input, ln1_g, ln1_b, pos, qp);

    // 2) value = mask-zero(source @ Wv + bv)
    {
        dim3 grid(DIM_/128, (MV + 63)/64);
        gemm_tc<<<grid, 128, GEMM_SMEM_BYTES>>>(source, Wv, bv, nullptr, mask, value, MV, DIM_, DIM_, 0);
    }
    // 3) offsets = qp @ Woff + boff
    {
        dim3 grid(DIM_/128, BQ/64);
        gemm_tc<<<grid, 128, GEMM_SMEM_BYTES>>>(qp, Woff, boff, nullptr, nullptr, off, BQ, DIM_, DIM_, 0);
    }
    // 4) attn logits = qp @ Wattn + battn
    {
        dim3 grid(1, BQ/64);
        gemm_tc<<<grid, 128, GEMM_SMEM_BYTES>>>(qp, Wattn, battn, nullptr, nullptr, attn, BQ, 128, DIM_, 0);
    }
    // 5) fused loc + softmax + deformable sampling (loc streamed to output)
    sample_kernel<<<BQ, 256>>>(value, off, attn, refp, out_loc, attnout);

    // 6) x = input + attnout @ Wout + bout
    {
        dim3 grid(DIM_/128, BQ/64);
        gemm_tc<<<grid, 128, GEMM_SMEM_BYTES>>>(attnout, Wout, bout, input, nullptr, xb, BQ, DIM_, DIM_, 0);
    }
    // 7) y = LN2(x)
    ln_kernel<<<BQ, 256>>>(xb, ln2_g, ln2_b, nullptr, yb);

    // 8) ffn = relu(y @ W1 + b1)
    {
        dim3 grid(DFF/128, BQ/64);
        gemm_tc<<<grid, 128, GEMM_SMEM_BYTES>>>(yb, W1, b1, nullptr, nullptr, ffn, BQ, DFF, DIM_, 1);
    }
    // 9) out_x = x + ffn @ W2 + b2
    {
        dim3 grid(DIM_/128, BQ/64);
        gemm_tc<<<grid, 128, GEMM_SMEM_BYTES>>>(ffn, W2, b2, xb, nullptr, out_x, BQ, DIM_, DFF, 0);
    }
}

// round 5
// speedup vs baseline: 1.1750x; 1.1750x over previous
#include <cuda_runtime.h>
#include <cstdint>

#define B_      8
#define Q_      2048
#define DIM_    256
#define NH      8
#define HD      32
#define DFF     1024
#define LEN_IN_ 13294
#define BQ      (B_*Q_)
#define MV      (B_*LEN_IN_)   // 106352 rows of the value GEMM

// ---------------- scratch (static device arrays; no allocation) ----------------
__device__ float g_qp[BQ*DIM_];
__device__ float g_value[MV*DIM_];
__device__ float g_off[BQ*DIM_];
__device__ float g_attn[BQ*128];
__device__ float g_attnout[BQ*DIM_];
__device__ float g_x[BQ*DIM_];
__device__ float g_y[BQ*DIM_];
__device__ float g_ffn[BQ*DFF];

// ---------------- LayerNorm (+ optional additive term) ----------------
__global__ __launch_bounds__(256) void ln_kernel(
    const float* __restrict__ x, const float* __restrict__ g,
    const float* __restrict__ b, const float* __restrict__ addend,
    float* __restrict__ out)
{
    __shared__ float sbuf[8];
    const int row = blockIdx.x;
    const int t = threadIdx.x;
    const float v = x[(size_t)row*DIM_ + t];

    float s = v;
    #pragma unroll
    for (int o = 16; o; o >>= 1) s += __shfl_xor_sync(0xffffffffu, s, o);
    if ((t & 31) == 0) sbuf[t >> 5] = s;
    __syncthreads();
    float mean = 0.f;
    #pragma unroll
    for (int i = 0; i < 8; i++) mean += sbuf[i];
    mean *= (1.f/256.f);

    const float d = v - mean;
    float s2 = d*d;
    #pragma unroll
    for (int o = 16; o; o >>= 1) s2 += __shfl_xor_sync(0xffffffffu, s2, o);
    __syncthreads();
    if ((t & 31) == 0) sbuf[t >> 5] = s2;
    __syncthreads();
    float var = 0.f;
    #pragma unroll
    for (int i = 0; i < 8; i++) var += sbuf[i];
    var *= (1.f/256.f);

    float r = d * rsqrtf(var + 1e-5f) * g[t] + b[t];
    if (addend) r += addend[(size_t)row*DIM_ + t];
    out[(size_t)row*DIM_ + t] = r;
}

// ---------------- tf32 helpers ----------------
__device__ __forceinline__ uint32_t f2tf32(float f) {
    uint32_t u;
    asm("cvt.rna.tf32.f32 %0, %1;" : "=r"(u) : "f"(f));
    return u;
}

__device__ __forceinline__ void mma_tf32(float c[4], const uint32_t a[4], const uint32_t b[2]) {
    asm("mma.sync.aligned.m16n8k8.row.col.f32.tf32.tf32.f32 "
        "{%0,%1,%2,%3}, {%4,%5,%6,%7}, {%8,%9}, {%0,%1,%2,%3};"
        : "+f"(c[0]), "+f"(c[1]), "+f"(c[2]), "+f"(c[3])
        : "r"(a[0]), "r"(a[1]), "r"(a[2]), "r"(a[3]), "r"(b[0]), "r"(b[1]));
}

__device__ __forceinline__ void cp_async16(void* smem_dst, const void* gsrc) {
    uint32_t s = (uint32_t)__cvta_generic_to_shared(smem_dst);
    asm volatile("cp.async.cg.shared.global [%0], [%1], 16;" :: "r"(s), "l"(gsrc));
}
__device__ __forceinline__ void cp_commit() { asm volatile("cp.async.commit_group;"); }
__device__ __forceinline__ void cp_wait0()  { asm volatile("cp.async.wait_group 0;"); }

// ---------------- TF32 tensor-core GEMM (ldmatrix + frag pipelined) ----------------
// C = act(A@B + bias) [+resid] [mask rows]
// A: [M,K] row-major, B: [K,N] row-major. N % 128 == 0, K % 32 == 0. M guarded.
// CTA tile 64x128, K-tile 32, 4 warps (warp tile 64x32).
// A: LDG -> cvt.rna -> STS.128 row-major (stride 36, conflict-free)
//    frags via ldmatrix.m8n8.x4 (conflict-free, 1 instr per 16x8 quad pair).
// B: cp.async double buffered; raw fp32 bits to MMA (tf32 truncation).
// Fragments double-buffered across kk so LDSM/LDS hides behind MMAs.
#define A_STR   36
#define A_STAGE (64*A_STR)             // 2304 words / stage
#define B_STR   136
#define B_STAGE (32*B_STR)             // 4352 words / stage
#define GEMM_SMEM_BYTES ((2*A_STAGE + 2*B_STAGE) * 4)   // 53248 B

__global__ __launch_bounds__(128, 3) void gemm_tc(
    const float* __restrict__ A, const float* __restrict__ Bm,
    const float* __restrict__ bias, const float* __restrict__ resid,
    const uint8_t* __restrict__ mask, float* __restrict__ C,
    int M, int N, int K, int relu)
{
    extern __shared__ float dynsmem[];
    uint32_t* As = (uint32_t*)dynsmem;           // [2][64][A_STR]
    float*    Bs = dynsmem + 2*A_STAGE;          // [2][32][B_STR]

    const int tid   = threadIdx.x;
    const int warpN = tid >> 5;
    const int lane  = tid & 31;
    const int gid   = lane >> 2;
    const int tig   = lane & 3;
    const int row0  = blockIdx.y * 64;
    const int col0  = blockIdx.x * 128;

    // A global-load slot: 16 floats (row a_row, k in [a_col, a_col+16))
    const int a_row = tid >> 1;
    const int a_col = (tid & 1) << 4;
    const bool avalid = (row0 + a_row) < M;
    const float* aptr = A + (size_t)(row0 + a_row) * K + a_col;

    // ldmatrix per-lane source: lanes 0-7 -> a0 rows, 8-15 -> a1, 16-23 -> a2, 24-31 -> a3
    const int lrow   = (lane & 7) + ((lane >> 3) & 1) * 8;  // row within 16-block
    const int lkhalf = (lane >> 4) & 1;                      // k half (0 or +4)
    const uint32_t a_sbase = (uint32_t)__cvta_generic_to_shared(As);

    float acc[4][4][4];
    #pragma unroll
    for (int i = 0; i < 4; i++)
        #pragma unroll
        for (int j = 0; j < 4; j++)
            #pragma unroll
            for (int r = 0; r < 4; r++) acc[i][j][r] = 0.f;

    const int nkt = K >> 5;
    float4 ra[4];

    // ---- prologue ----
    #pragma unroll
    for (int i = 0; i < 4; i++)
        ra[i] = avalid ? *(const float4*)(aptr + i*4) : make_float4(0.f,0.f,0.f,0.f);
    #pragma unroll
    for (int i = 0; i < 8; i++) {
        const int chunk = i*128 + tid;
        const int br = chunk >> 5;
        const int bn = (chunk & 31) << 2;
        cp_async16(&Bs[br*B_STR + bn], Bm + (size_t)br*N + col0 + bn);
    }
    cp_commit();
    #pragma unroll
    for (int i = 0; i < 4; i++) {
        uint4 w;
        w.x = f2tf32(ra[i].x); w.y = f2tf32(ra[i].y);
        w.z = f2tf32(ra[i].z); w.w = f2tf32(ra[i].w);
        *(uint4*)&As[a_row*A_STR + a_col + i*4] = w;
    }

    uint32_t af[2][4][4], bf[2][4][2];

    for (int t = 0; t < nkt; t++) {
        const int p = t & 1;
        cp_wait0();
        __syncthreads();

        const bool more = (t + 1) < nkt;
        if (more) {
            const int k0n = (t + 1) << 5;
            #pragma unroll
            for (int i = 0; i < 4; i++)
                ra[i] = avalid ? *(const float4*)(aptr + k0n + i*4)
                               : make_float4(0.f,0.f,0.f,0.f);
            float* bdst = Bs + (p ^ 1) * B_STAGE;
            #pragma unroll
            for (int i = 0; i < 8; i++) {
                const int chunk = i*128 + tid;
                const int br = chunk >> 5;
                const int bn = (chunk & 31) << 2;
                cp_async16(&bdst[br*B_STR + bn], Bm + (size_t)(k0n + br)*N + col0 + bn);
            }
            cp_commit();
        }

        // ---- compute stage p, fragments double-buffered over kk ----
        const uint32_t a_stage = a_sbase + (uint32_t)(p * A_STAGE * 4);
        const float*   bb      = Bs + p * B_STAGE;
        const int      cbase   = warpN * 32 + gid;

        // load kk = 0 fragments
        #pragma unroll
        for (int mt = 0; mt < 4; mt++) {
            const uint32_t addr = a_stage
                + (uint32_t)(((mt*16 + lrow)*A_STR + lkhalf*4) << 2);
            asm volatile("ldmatrix.sync.aligned.m8n8.x4.shared.b16 {%0,%1,%2,%3}, [%4];"
                : "=r"(af[0][mt][0]), "=r"(af[0][mt][1]),
                  "=r"(af[0][mt][2]), "=r"(af[0][mt][3]) : "r"(addr));
        }
        #pragma unroll
        for (int nt = 0; nt < 4; nt++) {
            bf[0][nt][0] = __float_as_uint(bb[(tig    )*B_STR + cbase + nt*8]);
            bf[0][nt][1] = __float_as_uint(bb[(tig + 4)*B_STR + cbase + nt*8]);
        }

        #pragma unroll
        for (int kk = 0; kk < 4; kk++) {
            const int cur = kk & 1;
            if (kk < 3) {
                const int nxt = cur ^ 1;
                const int kn  = kk + 1;
                #pragma unroll
                for (int mt = 0; mt < 4; mt++) {
                    const uint32_t addr = a_stage
                        + (uint32_t)(((mt*16 + lrow)*A_STR + kn*8 + lkhalf*4) << 2);
                    asm volatile("ldmatrix.sync.aligned.m8n8.x4.shared.b16 {%0,%1,%2,%3}, [%4];"
                        : "=r"(af[nxt][mt][0]), "=r"(af[nxt][mt][1]),
                          "=r"(af[nxt][mt][2]), "=r"(af[nxt][mt][3]) : "r"(addr));
                }
                #pragma unroll
                for (int nt = 0; nt < 4; nt++) {
                    bf[nxt][nt][0] = __float_as_uint(bb[(kn*8 + tig    )*B_STR + cbase + nt*8]);
                    bf[nxt][nt][1] = __float_as_uint(bb[(kn*8 + tig + 4)*B_STR + cbase + nt*8]);
                }
            }
            #pragma unroll
            for (int mt = 0; mt < 4; mt++)
                #pragma unroll
                for (int nt = 0; nt < 4; nt++)
                    mma_tf32(acc[mt][nt], af[cur][mt], bf[cur][nt]);
        }

        // ---- STS A(t+1) into other stage ----
        if (more) {
            uint32_t* adst = As + (p ^ 1) * A_STAGE;
            #pragma unroll
            for (int i = 0; i < 4; i++) {
                uint4 w;
                w.x = f2tf32(ra[i].x); w.y = f2tf32(ra[i].y);
                w.z = f2tf32(ra[i].z); w.w = f2tf32(ra[i].w);
                *(uint4*)&adst[a_row*A_STR + a_col + i*4] = w;
            }
        }
    }

    // ---- epilogue ----
    #pragma unroll
    for (int mt = 0; mt < 4; mt++) {
        #pragma unroll
        for (int half = 0; half < 2; half++) {
            const int r = row0 + mt*16 + gid + half*8;
            if (r >= M) continue;
            const float mz = (mask && mask[r]) ? 0.f : 1.f;
            #pragma unroll
            for (int nt = 0; nt < 4; nt++) {
                const int c = col0 + warpN*32 + nt*8 + 2*tig;
                float v0 = acc[mt][nt][half*2 + 0] + bias[c + 0];
                float v1 = acc[mt][nt][half*2 + 1] + bias[c + 1];
                if (relu) { v0 = fmaxf(v0, 0.f); v1 = fmaxf(v1, 0.f); }
                if (resid) {
                    const float* rp = resid + (size_t)r*N + c;
                    v0 += rp[0]; v1 += rp[1];
                }
                float2 vv = make_float2(v0*mz, v1*mz);
                *(float2*)(C + (size_t)r*N + c) = vv;
            }
        }
    }
}

// ---------------- fused loc + softmax + MS-deformable bilinear sampling ----------------
__global__ __launch_bounds__(256) void sample_kernel(
    const float* __restrict__ value, const float* __restrict__ off,
    const float* __restrict__ attnlog, const float* __restrict__ ref,
    float* __restrict__ out_loc, float* __restrict__ out)
{
    __shared__ float s_loc[256];
    __shared__ float s_attn[128];

    const int bq   = blockIdx.x;
    const int tid  = threadIdx.x;
    const int h    = tid >> 5;
    const int lane = tid & 31;
    const int b    = bq >> 11;

    {
        const int c = tid & 1;
        const int l = (tid >> 3) & 3;
        const float nd[4] = {100.f, 50.f, 25.f, 13.f};
        const float v = ref[((size_t)bq*4 + l)*2 + c]
                      + off[(size_t)bq*256 + tid] / nd[l];
        s_loc[tid] = v;
        out_loc[(size_t)bq*256 + tid] = v;
    }
    if (tid < 128) {
        const float logit = attnlog[(size_t)bq*128 + tid];
        float m = logit;
        #pragma unroll
        for (int o = 8; o; o >>= 1) m = fmaxf(m, __shfl_xor_sync(0xffffffffu, m, o, 16));
        const float e = __expf(logit - m);
        float s = e;
        #pragma unroll
        for (int o = 8; o; o >>= 1) s += __shfl_xor_sync(0xffffffffu, s, o, 16);
        s_attn[tid] = e / s;
    }
    __syncthreads();

    const float* locp = s_loc  + h*32;
    const float* ap   = s_attn + h*16;

    constexpr int LH[4] = {100, 50, 25, 13};
    constexpr int LS[4] = {0, 10000, 12500, 13125};

    float acc = 0.f;
    #pragma unroll
    for (int l = 0; l < 4; l++) {
        const int Hh = LH[l], Ww = LH[l];
        const float* vb = value + ((size_t)b*LEN_IN_ + LS[l])*DIM_ + h*32 + lane;
        #pragma unroll
        for (int p = 0; p < 4; p++) {
            const float lx = locp[(l*4 + p)*2 + 0];
            const float ly = locp[(l*4 + p)*2 + 1];
            const float a  = ap[l*4 + p];
            const float x = lx * (float)Ww - 0.5f;
            const float y = ly * (float)Hh - 0.5f;
            const float x0f = floorf(x), y0f = floorf(y);
            const float wx = x - x0f, wy = y - y0f;
            const int x0 = (int)x0f, y0 = (int)y0f;
            const int x1 = x0 + 1,  y1 = y0 + 1;

            const float vx0 = (x0 >= 0 && x0 < Ww) ? 1.f : 0.f;
            const float vx1 = (x1 >= 0 && x1 < Ww) ? 1.f : 0.f;
            const float vy0 = (y0 >= 0 && y0 < Hh) ? 1.f : 0.f;
            const float vy1 = (y1 >= 0 && y1 < Hh) ? 1.f : 0.f;
            const int cx0 = min(max(x0, 0), Ww-1);
            const int cx1 = min(max(x1, 0), Ww-1);
            const int cy0 = min(max(y0, 0), Hh-1);
            const int cy1 = min(max(y1, 0), Hh-1);

            const float g00 = vb[(size_t)(cy0*Ww + cx0)*DIM_] * (vx0*vy0);
            const float g01 = vb[(size_t)(cy0*Ww + cx1)*DIM_] * (vx1*vy0);
            const float g10 = vb[(size_t)(cy1*Ww + cx0)*DIM_] * (vx0*vy1);
            const float g11 = vb[(size_t)(cy1*Ww + cx1)*DIM_] * (vx1*vy1);

            const float top = g00*(1.f-wx) + g01*wx;
            const float bot = g10*(1.f-wx) + g11*wx;
            acc += a * (top*(1.f-wy) + bot*wy);
        }
    }
    out[(size_t)bq*256 + h*32 + lane] = acc;
}

// ---------------- launch ----------------
extern "C" void kernel_launch(void* const* d_in, const int* in_sizes, int n_in,
                              void* d_out, int out_size)
{
    const float*   input  = (const float*)d_in[0];
    const float*   pos    = (const float*)d_in[1];
    const float*   refp   = (const float*)d_in[2];
    const float*   source = (const float*)d_in[3];
    const uint8_t* mask   = (const uint8_t*)d_in[6];
    const float*   ln1_g  = (const float*)d_in[7];
    const float*   ln1_b  = (const float*)d_in[8];
    const float*   ln2_g  = (const float*)d_in[9];
    const float*   ln2_b  = (const float*)d_in[10];
    const float*   Wv     = (const float*)d_in[11];
    const float*   bv     = (const float*)d_in[12];
    const float*   Woff   = (const float*)d_in[13];
    const float*   boff   = (const float*)d_in[14];
    const float*   Wattn  = (const float*)d_in[15];
    const float*   battn  = (const float*)d_in[16];
    const float*   Wout   = (const float*)d_in[17];
    const float*   bout   = (const float*)d_in[18];
    const float*   W1     = (const float*)d_in[19];
    const float*   b1     = (const float*)d_in[20];
    const float*   W2     = (const float*)d_in[21];
    const float*   b2     = (const float*)d_in[22];

    float* out_x   = (float*)d_out;
    float* out_loc = (float*)d_out + (size_t)BQ*DIM_;

    float *qp, *value, *off, *attn, *attnout, *xb, *yb, *ffn;
    cudaGetSymbolAddress((void**)&qp,      g_qp);
    cudaGetSymbolAddress((void**)&value,   g_value);
    cudaGetSymbolAddress((void**)&off,     g_off);
    cudaGetSymbolAddress((void**)&attn,    g_attn);
    cudaGetSymbolAddress((void**)&attnout, g_attnout);
    cudaGetSymbolAddress((void**)&xb,      g_x);
    cudaGetSymbolAddress((void**)&yb,      g_y);
    cudaGetSymbolAddress((void**)&ffn,     g_ffn);

    cudaFuncSetAttribute(gemm_tc, cudaFuncAttributeMaxDynamicSharedMemorySize,
                         GEMM_SMEM_BYTES);

    // 1) qp = LN1(input) + pos
    ln_kernel<<<BQ, 256>>>(input, ln1_g, ln1_b, pos, qp);

    // 2) value = mask-zero(source @ Wv + bv)
    {
        dim3 grid(DIM_/128, (MV + 63)/64);
        gemm_tc<<<grid, 128, GEMM_SMEM_BYTES>>>(source, Wv, bv, nullptr, mask, value, MV, DIM_, DIM_, 0);
    }
    // 3) offsets = qp @ Woff + boff
    {
        dim3 grid(DIM_/128, BQ/64);
        gemm_tc<<<grid, 128, GEMM_SMEM_BYTES>>>(qp, Woff, boff, nullptr, nullptr, off, BQ, DIM_, DIM_, 0);
    }
    // 4) attn logits = qp @ Wattn + battn
    {
        dim3 grid(1, BQ/64);
        gemm_tc<<<grid, 128, GEMM_SMEM_BYTES>>>(qp, Wattn, battn, nullptr, nullptr, attn, BQ, 128, DIM_, 0);
    }
    // 5) fused loc + softmax + deformable sampling
    sample_kernel<<<BQ, 256>>>(value, off, attn, refp, out_loc, attnout);

    // 6) x = input + attnout @ Wout + bout
    {
        dim3 grid(DIM_/128, BQ/64);
        gemm_tc<<<grid, 128, GEMM_SMEM_BYTES>>>(attnout, Wout, bout, input, nullptr, xb, BQ, DIM_, DIM_, 0);
    }
    // 7) y = LN2(x)
    ln_kernel<<<BQ, 256>>>(xb, ln2_g, ln2_b, nullptr, yb);

    // 8) ffn = relu(y @ W1 + b1)
    {
        dim3 grid(DFF/128, BQ/64);
        gemm_tc<<<grid, 128, GEMM_SMEM_BYTES>>>(yb, W1, b1, nullptr, nullptr, ffn, BQ, DFF, DIM_, 1);
    }
    // 9) out_x = x + ffn @ W2 + b2
    {
        dim3 grid(DIM_/128, BQ/64);
        gemm_tc<<<grid, 128, GEMM_SMEM_BYTES>>>(ffn, W2, b2, xb, nullptr, out_x, BQ, DIM_, DFF, 0);
    }
}

// round 7
// speedup vs baseline: 1.3025x; 1.1086x over previous
#include <cuda_runtime.h>
#include <cuda_bf16.h>
#include <cstdint>

#define B_      8
#define Q_      2048
#define DIM_    256
#define NH      8
#define HD      32
#define DFF     1024
#define LEN_IN_ 13294
#define BQ      (B_*Q_)
#define MV      (B_*LEN_IN_)

// ---------------- scratch ----------------
__device__ float    g_qp[BQ*DIM_];
__device__ float    g_value[MV*DIM_];
__device__ float    g_off[BQ*DIM_];
__device__ float    g_attn[BQ*128];
__device__ float    g_attnout[BQ*DIM_];
__device__ float    g_x[BQ*DIM_];
__device__ float    g_y[BQ*DIM_];
__device__ float    g_ffn[BQ*DFF];
__device__ uint32_t g_wp[376832];     // packed bf16x2 weights, [K/2][N] word layout

// packed-weight offsets (words)
#define WP_WV    0
#define WP_WOFF  32768
#define WP_WATTN 65536
#define WP_WOUT  81920
#define WP_W1    114688
#define WP_W2    245760

// ---------------- LayerNorm (+ optional additive term) ----------------
__global__ __launch_bounds__(256) void ln_kernel(
    const float* __restrict__ x, const float* __restrict__ g,
    const float* __restrict__ b, const float* __restrict__ addend,
    float* __restrict__ out)
{
    __shared__ float sbuf[8];
    const int row = blockIdx.x;
    const int t = threadIdx.x;
    const float v = x[(size_t)row*DIM_ + t];

    float s = v;
    #pragma unroll
    for (int o = 16; o; o >>= 1) s += __shfl_xor_sync(0xffffffffu, s, o);
    if ((t & 31) == 0) sbuf[t >> 5] = s;
    __syncthreads();
    float mean = 0.f;
    #pragma unroll
    for (int i = 0; i < 8; i++) mean += sbuf[i];
    mean *= (1.f/256.f);

    const float d = v - mean;
    float s2 = d*d;
    #pragma unroll
    for (int o = 16; o; o >>= 1) s2 += __shfl_xor_sync(0xffffffffu, s2, o);
    __syncthreads();
    if ((t & 31) == 0) sbuf[t >> 5] = s2;
    __syncthreads();
    float var = 0.f;
    #pragma unroll
    for (int i = 0; i < 8; i++) var += sbuf[i];
    var *= (1.f/256.f);

    float r = d * rsqrtf(var + 1e-5f) * g[t] + b[t];
    if (addend) r += addend[(size_t)row*DIM_ + t];
    out[(size_t)row*DIM_ + t] = r;
}

// ---------------- helpers ----------------
__device__ __forceinline__ uint32_t packbf(float lo, float hi) {
    uint32_t d;
    asm("cvt.rn.bf16x2.f32 %0, %1, %2;" : "=r"(d) : "f"(hi), "f"(lo));
    return d;
}

__device__ __forceinline__ void mma_bf16(float c[4], const uint32_t a[4], const uint32_t b[2]) {
    asm("mma.sync.aligned.m16n8k16.row.col.f32.bf16.bf16.f32 "
        "{%0,%1,%2,%3}, {%4,%5,%6,%7}, {%8,%9}, {%0,%1,%2,%3};"
        : "+f"(c[0]), "+f"(c[1]), "+f"(c[2]), "+f"(c[3])
        : "r"(a[0]), "r"(a[1]), "r"(a[2]), "r"(a[3]), "r"(b[0]), "r"(b[1]));
}

__device__ __forceinline__ void cp_async16(void* smem_dst, const void* gsrc) {
    uint32_t s = (uint32_t)__cvta_generic_to_shared(smem_dst);
    asm volatile("cp.async.cg.shared.global [%0], [%1], 16;" :: "r"(s), "l"(gsrc));
}
__device__ __forceinline__ void cp_commit() { asm volatile("cp.async.commit_group;"); }
__device__ __forceinline__ void cp_wait0()  { asm volatile("cp.async.wait_group 0;"); }

// ---------------- weight pack: W fp32 [K,N] -> words [K/2][N] of (bf16 k, bf16 k+1) ----
__global__ __launch_bounds__(256) void wconv_kernel(
    const float* __restrict__ W, uint32_t* __restrict__ out, int KP, int N)
{
    const int idx = blockIdx.x * 256 + threadIdx.x;
    if (idx >= KP * N) return;
    const int kp = idx / N;
    const int n  = idx - kp * N;
    const float lo = W[(size_t)(2*kp)     * N + n];
    const float hi = W[(size_t)(2*kp + 1) * N + n];
    out[idx] = packbf(lo, hi);
}

// ---------------- BF16 tensor-core GEMM ----------------
// C = act(A@B + bias) [+resid] [mask rows]
// A: fp32 [M,K] row-major (converted to bf16 in-kernel).
// Wp: packed bf16-pair words [K/2][N]. N % 128 == 0, K % 32 == 0. M guarded.
// CTA tile 64x128, K-tile 32 (= 2 k-steps of m16n8k16), 4 warps (warp tile 64x32).
#define A_STRB  80                       // padded A row stride bytes (32 bf16 -> 80B)
#define A_STAGEB (64*A_STRB)             // 5120 B
#define B_STRW  136                      // padded B row stride words
#define B_STAGEB (16*B_STRW*4)           // 8704 B
#define GEMM_SMEM_BYTES (2*A_STAGEB + 2*B_STAGEB)   // 27648 B

__global__ __launch_bounds__(128, 3) void gemm_bf(
    const float* __restrict__ A, const uint32_t* __restrict__ Wp,
    const float* __restrict__ bias, const float* __restrict__ resid,
    const uint8_t* __restrict__ mask, float* __restrict__ C,
    int M, int N, int K, int relu)
{
    extern __shared__ char smem[];
    char*     As = smem;                          // [2][64][A_STRB]
    uint32_t* Bs = (uint32_t*)(smem + 2*A_STAGEB); // [2][16][B_STRW]

    const int tid   = threadIdx.x;
    const int warpN = tid >> 5;
    const int lane  = tid & 31;
    const int gid   = lane >> 2;
    const int tig   = lane & 3;
    const int row0  = blockIdx.y * 64;
    const int col0  = blockIdx.x * 128;

    // A global-load slot: 16 floats (row a_row, k in [a_half*16, +16))
    const int a_row  = tid >> 1;
    const int a_half = tid & 1;
    const bool avalid = (row0 + a_row) < M;
    const float* aptr = A + (size_t)(row0 + a_row) * K + a_half*16;

    // ldmatrix lane addressing (m8n8.x4 b16): 4 matrices = (rows 0-7/8-15) x (k 0-7/8-15)
    const int lrow   = (lane & 7) + (((lane >> 3) & 1) << 3);
    const int lkhalf = (lane >> 4) & 1;
    const uint32_t a_sbase = (uint32_t)__cvta_generic_to_shared(As);

    float acc[4][4][4];
    #pragma unroll
    for (int i = 0; i < 4; i++)
        #pragma unroll
        for (int j = 0; j < 4; j++)
            #pragma unroll
            for (int r = 0; r < 4; r++) acc[i][j][r] = 0.f;

    const int nkt = K >> 5;
    const int KPW = N;                  // words per kp-row of Wp
    float4 ra[4];

    auto fillB = [&](int p, int t) {
        uint32_t* bdst = Bs + p * (B_STAGEB/4);
        const uint32_t* gB = Wp + (size_t)(t*16) * KPW + col0;
        #pragma unroll
        for (int i = 0; i < 4; i++) {
            const int c = i*128 + tid;          // 512 chunks of 16B
            const int r = c >> 5;               // kp row 0..15
            const int q = c & 31;               // 16B chunk in row
            cp_async16(&bdst[r*B_STRW + q*4], gB + (size_t)r*KPW + q*4);
        }
    };
    auto stsA = [&](int p) {
        uint32_t w[8];
        #pragma unroll
        for (int i = 0; i < 4; i++) {
            w[i*2+0] = packbf(ra[i].x, ra[i].y);
            w[i*2+1] = packbf(ra[i].z, ra[i].w);
        }
        char* dst = As + p*A_STAGEB + a_row*A_STRB + a_half*32;
        *(uint4*)(dst)      = make_uint4(w[0], w[1], w[2], w[3]);
        *(uint4*)(dst + 16) = make_uint4(w[4], w[5], w[6], w[7]);
    };

    // ---- prologue: stage 0 ----
    #pragma unroll
    for (int i = 0; i < 4; i++)
        ra[i] = avalid ? *(const float4*)(aptr + i*4) : make_float4(0.f,0.f,0.f,0.f);
    fillB(0, 0);
    cp_commit();
    stsA(0);

    uint32_t af[2][4][4], bf[2][4][2];

    for (int t = 0; t < nkt; t++) {
        const int p = t & 1;
        cp_wait0();
        __syncthreads();

        const bool more = (t + 1) < nkt;
        if (more) {
            const int k0n = (t + 1) << 5;
            #pragma unroll
            for (int i = 0; i < 4; i++)
                ra[i] = avalid ? *(const float4*)(aptr + k0n + i*4)
                               : make_float4(0.f,0.f,0.f,0.f);
            fillB(p ^ 1, t + 1);
            cp_commit();
        }

        // ---- compute stage p: 2 k-steps, fragments double-buffered ----
        const uint32_t a_stage = a_sbase + (uint32_t)(p * A_STAGEB);
        const uint32_t* bb     = Bs + p * (B_STAGEB/4);
        const int cbase        = warpN * 32 + gid;

        #pragma unroll
        for (int mt = 0; mt < 4; mt++) {
            const uint32_t addr = a_stage
                + (uint32_t)((mt*16 + lrow)*A_STRB + lkhalf*16);
            asm volatile("ldmatrix.sync.aligned.m8n8.x4.shared.b16 {%0,%1,%2,%3}, [%4];"
                : "=r"(af[0][mt][0]), "=r"(af[0][mt][1]),
                  "=r"(af[0][mt][2]), "=r"(af[0][mt][3]) : "r"(addr));
        }
        #pragma unroll
        for (int nt = 0; nt < 4; nt++) {
            bf[0][nt][0] = bb[(tig    )*B_STRW + cbase + nt*8];
            bf[0][nt][1] = bb[(tig + 4)*B_STRW + cbase + nt*8];
        }

        #pragma unroll
        for (int ks = 0; ks < 2; ks++) {
            if (ks == 0) {
                #pragma unroll
                for (int mt = 0; mt < 4; mt++) {
                    const uint32_t addr = a_stage
                        + (uint32_t)((mt*16 + lrow)*A_STRB + 32 + lkhalf*16);
                    asm volatile("ldmatrix.sync.aligned.m8n8.x4.shared.b16 {%0,%1,%2,%3}, [%4];"
                        : "=r"(af[1][mt][0]), "=r"(af[1][mt][1]),
                          "=r"(af[1][mt][2]), "=r"(af[1][mt][3]) : "r"(addr));
                }
                #pragma unroll
                for (int nt = 0; nt < 4; nt++) {
                    bf[1][nt][0] = bb[(8 + tig    )*B_STRW + cbase + nt*8];
                    bf[1][nt][1] = bb[(8 + tig + 4)*B_STRW + cbase + nt*8];
                }
            }
            #pragma unroll
            for (int mt = 0; mt < 4; mt++)
                #pragma unroll
                for (int nt = 0; nt < 4; nt++)
                    mma_bf16(acc[mt][nt], af[ks][mt], bf[ks][nt]);
        }

        if (more) stsA(p ^ 1);
    }

    // ---- epilogue ----
    #pragma unroll
    for (int mt = 0; mt < 4; mt++) {
        #pragma unroll
        for (int half = 0; half < 2; half++) {
            const int r = row0 + mt*16 + gid + half*8;
            if (r >= M) continue;
            const float mz = (mask && mask[r]) ? 0.f : 1.f;
            #pragma unroll
            for (int nt = 0; nt < 4; nt++) {
                const int c = col0 + warpN*32 + nt*8 + 2*tig;
                float v0 = acc[mt][nt][half*2 + 0] + bias[c + 0];
                float v1 = acc[mt][nt][half*2 + 1] + bias[c + 1];
                if (relu) { v0 = fmaxf(v0, 0.f); v1 = fmaxf(v1, 0.f); }
                if (resid) {
                    const float* rp = resid + (size_t)r*N + c;
                    v0 += rp[0]; v1 += rp[1];
                }
                float2 vv = make_float2(v0*mz, v1*mz);
                *(float2*)(C + (size_t)r*N + c) = vv;
            }
        }
    }
}

// ---------------- fused loc + softmax + MS-deformable sampling ----------------
__global__ __launch_bounds__(256) void sample_kernel(
    const float* __restrict__ value, const float* __restrict__ off,
    const float* __restrict__ attnlog, const float* __restrict__ ref,
    float* __restrict__ out_loc, float* __restrict__ out)
{
    __shared__ float s_loc[256];
    __shared__ float s_attn[128];

    const int bq   = blockIdx.x;
    const int tid  = threadIdx.x;
    const int h    = tid >> 5;
    const int lane = tid & 31;
    const int b    = bq >> 11;

    {
        const int c = tid & 1;
        const int l = (tid >> 3) & 3;
        const float nd[4] = {100.f, 50.f, 25.f, 13.f};
        const float v = ref[((size_t)bq*4 + l)*2 + c]
                      + off[(size_t)bq*256 + tid] / nd[l];
        s_loc[tid] = v;
        out_loc[(size_t)bq*256 + tid] = v;
    }
    if (tid < 128) {
        const float logit = attnlog[(size_t)bq*128 + tid];
        float m = logit;
        #pragma unroll
        for (int o = 8; o; o >>= 1) m = fmaxf(m, __shfl_xor_sync(0xffffffffu, m, o, 16));
        const float e = __expf(logit - m);
        float s = e;
        #pragma unroll
        for (int o = 8; o; o >>= 1) s += __shfl_xor_sync(0xffffffffu, s, o, 16);
        s_attn[tid] = e / s;
    }
    __syncthreads();

    const float* locp = s_loc  + h*32;
    const float* ap   = s_attn + h*16;

    constexpr int LH[4] = {100, 50, 25, 13};
    constexpr int LS[4] = {0, 10000, 12500, 13125};

    float acc = 0.f;
    #pragma unroll
    for (int l = 0; l < 4; l++) {
        const int Hh = LH[l], Ww = LH[l];
        const float* vb = value + ((size_t)b*LEN_IN_ + LS[l])*DIM_ + h*32 + lane;
        #pragma unroll
        for (int p = 0; p < 4; p++) {
            const float lx = locp[(l*4 + p)*2 + 0];
            const float ly = locp[(l*4 + p)*2 + 1];
            const float a  = ap[l*4 + p];
            const float x = lx * (float)Ww - 0.5f;
            const float y = ly * (float)Hh - 0.5f;
            const float x0f = floorf(x), y0f = floorf(y);
            const float wx = x - x0f, wy = y - y0f;
            const int x0 = (int)x0f, y0 = (int)y0f;
            const int x1 = x0 + 1,  y1 = y0 + 1;

            const float vx0 = (x0 >= 0 && x0 < Ww) ? 1.f : 0.f;
            const float vx1 = (x1 >= 0 && x1 < Ww) ? 1.f : 0.f;
            const float vy0 = (y0 >= 0 && y0 < Hh) ? 1.f : 0.f;
            const float vy1 = (y1 >= 0 && y1 < Hh) ? 1.f : 0.f;
            const int cx0 = min(max(x0, 0), Ww-1);
            const int cx1 = min(max(x1, 0), Ww-1);
            const int cy0 = min(max(y0, 0), Hh-1);
            const int cy1 = min(max(y1, 0), Hh-1);

            const float g00 = vb[(size_t)(cy0*Ww + cx0)*DIM_] * (vx0*vy0);
            const float g01 = vb[(size_t)(cy0*Ww + cx1)*DIM_] * (vx1*vy0);
            const float g10 = vb[(size_t)(cy1*Ww + cx0)*DIM_] * (vx0*vy1);
            const float g11 = vb[(size_t)(cy1*Ww + cx1)*DIM_] * (vx1*vy1);

            const float top = g00*(1.f-wx) + g01*wx;
            const float bot = g10*(1.f-wx) + g11*wx;
            acc += a * (top*(1.f-wy) + bot*wy);
        }
    }
    out[(size_t)bq*256 + h*32 + lane] = acc;
}

// ---------------- launch ----------------
extern "C" void kernel_launch(void* const* d_in, const int* in_sizes, int n_in,
                              void* d_out, int out_size)
{
    const float*   input  = (const float*)d_in[0];
    const float*   pos    = (const float*)d_in[1];
    const float*   refp   = (const float*)d_in[2];
    const float*   source = (const float*)d_in[3];
    const uint8_t* mask   = (const uint8_t*)d_in[6];
    const float*   ln1_g  = (const float*)d_in[7];
    const float*   ln1_b  = (const float*)d_in[8];
    const float*   ln2_g  = (const float*)d_in[9];
    const float*   ln2_b  = (const float*)d_in[10];
    const float*   Wv     = (const float*)d_in[11];
    const float*   bv     = (const float*)d_in[12];
    const float*   Woff   = (const float*)d_in[13];
    const float*   boff   = (const float*)d_in[14];
    const float*   Wattn  = (const float*)d_in[15];
    const float*   battn  = (const float*)d_in[16];
    const float*   Wout   = (const float*)d_in[17];
    const float*   bout   = (const float*)d_in[18];
    const float*   W1     = (const float*)d_in[19];
    const float*   b1     = (const float*)d_in[20];
    const float*   W2     = (const float*)d_in[21];
    const float*   b2     = (const float*)d_in[22];

    float* out_x   = (float*)d_out;
    float* out_loc = (float*)d_out + (size_t)BQ*DIM_;

    float *qp, *value, *off, *attn, *attnout, *xb, *yb, *ffn;
    uint32_t* wp;
    cudaGetSymbolAddress((void**)&qp,      g_qp);
    cudaGetSymbolAddress((void**)&value,   g_value);
    cudaGetSymbolAddress((void**)&off,     g_off);
    cudaGetSymbolAddress((void**)&attn,    g_attn);
    cudaGetSymbolAddress((void**)&attnout, g_attnout);
    cudaGetSymbolAddress((void**)&xb,      g_x);
    cudaGetSymbolAddress((void**)&yb,      g_y);
    cudaGetSymbolAddress((void**)&ffn,     g_ffn);
    cudaGetSymbolAddress((void**)&wp,      g_wp);

    cudaFuncSetAttribute(gemm_bf, cudaFuncAttributeMaxDynamicSharedMemorySize,
                         GEMM_SMEM_BYTES);

    // 0) pack weights to bf16 pairs
    wconv_kernel<<<(128*256 + 255)/256, 256>>>(Wv,    wp + WP_WV,    128, 256);
    wconv_kernel<<<(128*256 + 255)/256, 256>>>(Woff,  wp + WP_WOFF,  128, 256);
    wconv_kernel<<<(128*128 + 255)/256, 256>>>(Wattn, wp + WP_WATTN, 128, 128);
    wconv_kernel<<<(128*256 + 255)/256, 256>>>(Wout,  wp + WP_WOUT,  128, 256);
    wconv_kernel<<<(128*1024 + 255)/256, 256>>>(W1,   wp + WP_W1,    128, 1024);
    wconv_kernel<<<(512*256 + 255)/256, 256>>>(W2,    wp + WP_W2,    512, 256);

    // 1) qp = LN1(input) + pos
    ln_kernel<<<BQ, 256>>>(input, ln1_g, ln1_b, pos, qp);

    // 2) value = mask-zero(source @ Wv + bv)
    {
        dim3 grid(DIM_/128, (MV + 63)/64);
        gemm_bf<<<grid, 128, GEMM_SMEM_BYTES>>>(source, wp + WP_WV, bv, nullptr, mask, value, MV, DIM_, DIM_, 0);
    }
    // 3) offsets = qp @ Woff + boff
    {
        dim3 grid(DIM_/128, BQ/64);
        gemm_bf<<<grid, 128, GEMM_SMEM_BYTES>>>(qp, wp + WP_WOFF, boff, nullptr, nullptr, off, BQ, DIM_, DIM_, 0);
    }
    // 4) attn logits = qp @ Wattn + battn
    {
        dim3 grid(1, BQ/64);
        gemm_bf<<<grid, 128, GEMM_SMEM_BYTES>>>(qp, wp + WP_WATTN, battn, nullptr, nullptr, attn, BQ, 128, DIM_, 0);
    }
    // 5) fused loc + softmax + deformable sampling
    sample_kernel<<<BQ, 256>>>(value, off, attn, refp, out_loc, attnout);

    // 6) x = input + attnout @ Wout + bout
    {
        dim3 grid(DIM_/128, BQ/64);
        gemm_bf<<<grid, 128, GEMM_SMEM_BYTES>>>(attnout, wp + WP_WOUT, bout, input, nullptr, xb, BQ, DIM_, DIM_, 0);
    }
    // 7) y = LN2(x)
    ln_kernel<<<BQ, 256>>>(xb, ln2_g, ln2_b, nullptr, yb);

    // 8) ffn = relu(y @ W1 + b1)
    {
        dim3 grid(DFF/128, BQ/64);
        gemm_bf<<<grid, 128, GEMM_SMEM_BYTES>>>(yb, wp + WP_W1, b1, nullptr, nullptr, ffn, BQ, DFF, DIM_, 1);
    }
    // 9) out_x = x + ffn @ W2 + b2
    {
        dim3 grid(DIM_/128, BQ/64);
        gemm_bf<<<grid, 128, GEMM_SMEM_BYTES>>>(ffn, wp + WP_W2, b2, xb, nullptr, out_x, BQ, DIM_, DFF, 0);
    }
}

// round 8
// speedup vs baseline: 1.5984x; 1.2271x over previous
#include <cuda_runtime.h>
#include <cuda_bf16.h>
#include <cuda_fp16.h>
#include <cstdint>

#define B_      8
#define Q_      2048
#define DIM_    256
#define NH      8
#define HD      32
#define DFF     1024
#define LEN_IN_ 13294
#define BQ      (B_*Q_)
#define MV      (B_*LEN_IN_)

// ---------------- scratch ----------------
__device__ float    g_qp[BQ*DIM_];
__device__ __half   g_valh[MV*DIM_];       // fp16 value (54 MB, L2-resident)
__device__ float    g_offattn[BQ*384];     // [off(256) | attn logits(128)] per row
__device__ float    g_attnout[BQ*DIM_];
__device__ float    g_x[BQ*DIM_];
__device__ float    g_y[BQ*DIM_];
__device__ float    g_ffn[BQ*DFF];
__device__ uint32_t g_wp[376832];          // packed bf16x2 weights
__device__ float    g_bcat[384];           // concat bias [boff | battn]

// packed-weight word offsets
#define WP_WV    0
#define WP_PROJ  32768                     // [128][384] Woff++Wattn
#define WP_WOUT  81920
#define WP_W1    114688
#define WP_W2    245760

// ---------------- LayerNorm (+ optional additive term) ----------------
__global__ __launch_bounds__(256) void ln_kernel(
    const float* __restrict__ x, const float* __restrict__ g,
    const float* __restrict__ b, const float* __restrict__ addend,
    float* __restrict__ out)
{
    __shared__ float sbuf[8];
    const int row = blockIdx.x;
    const int t = threadIdx.x;
    const float v = x[(size_t)row*DIM_ + t];

    float s = v;
    #pragma unroll
    for (int o = 16; o; o >>= 1) s += __shfl_xor_sync(0xffffffffu, s, o);
    if ((t & 31) == 0) sbuf[t >> 5] = s;
    __syncthreads();
    float mean = 0.f;
    #pragma unroll
    for (int i = 0; i < 8; i++) mean += sbuf[i];
    mean *= (1.f/256.f);

    const float d = v - mean;
    float s2 = d*d;
    #pragma unroll
    for (int o = 16; o; o >>= 1) s2 += __shfl_xor_sync(0xffffffffu, s2, o);
    __syncthreads();
    if ((t & 31) == 0) sbuf[t >> 5] = s2;
    __syncthreads();
    float var = 0.f;
    #pragma unroll
    for (int i = 0; i < 8; i++) var += sbuf[i];
    var *= (1.f/256.f);

    float r = d * rsqrtf(var + 1e-5f) * g[t] + b[t];
    if (addend) r += addend[(size_t)row*DIM_ + t];
    out[(size_t)row*DIM_ + t] = r;
}

// ---------------- helpers ----------------
__device__ __forceinline__ uint32_t packbf(float lo, float hi) {
    uint32_t d;
    asm("cvt.rn.bf16x2.f32 %0, %1, %2;" : "=r"(d) : "f"(hi), "f"(lo));
    return d;
}

__device__ __forceinline__ void mma_bf16(float c[4], const uint32_t a[4], const uint32_t b[2]) {
    asm("mma.sync.aligned.m16n8k16.row.col.f32.bf16.bf16.f32 "
        "{%0,%1,%2,%3}, {%4,%5,%6,%7}, {%8,%9}, {%0,%1,%2,%3};"
        : "+f"(c[0]), "+f"(c[1]), "+f"(c[2]), "+f"(c[3])
        : "r"(a[0]), "r"(a[1]), "r"(a[2]), "r"(a[3]), "r"(b[0]), "r"(b[1]));
}

__device__ __forceinline__ void cp_async16(void* smem_dst, const void* gsrc) {
    uint32_t s = (uint32_t)__cvta_generic_to_shared(smem_dst);
    asm volatile("cp.async.cg.shared.global [%0], [%1], 16;" :: "r"(s), "l"(gsrc));
}
__device__ __forceinline__ void cp_commit() { asm volatile("cp.async.commit_group;"); }
__device__ __forceinline__ void cp_wait0()  { asm volatile("cp.async.wait_group 0;"); }

// ---------------- single-launch weight pack ----------------
// Packs all weights to bf16-pair words; Woff & Wattn interleave into one
// [128][384] matrix; also builds the concat bias.
struct WPackArgs {
    const float *Wv, *Woff, *Wattn, *Wout, *W1, *W2, *boff, *battn;
};
__global__ __launch_bounds__(256) void wconv_all(WPackArgs a, uint32_t* __restrict__ out,
                                                 float* __restrict__ bcat)
{
    int idx = blockIdx.x * 256 + threadIdx.x;
    // seg 0: Wv [128][256]
    if (idx < 32768) {
        const int kp = idx >> 8, n = idx & 255;
        out[WP_WV + idx] = packbf(a.Wv[(size_t)(2*kp)*256 + n], a.Wv[(size_t)(2*kp+1)*256 + n]);
        return;
    }
    idx -= 32768;
    // seg 1: projcat [128][384] = Woff(256) ++ Wattn(128)
    if (idx < 49152) {
        const int kp = idx / 384, n = idx - kp*384;
        float lo, hi;
        if (n < 256) {
            lo = a.Woff[(size_t)(2*kp)*256 + n];  hi = a.Woff[(size_t)(2*kp+1)*256 + n];
        } else {
            lo = a.Wattn[(size_t)(2*kp)*128 + n-256]; hi = a.Wattn[(size_t)(2*kp+1)*128 + n-256];
        }
        out[WP_PROJ + idx] = packbf(lo, hi);
        return;
    }
    idx -= 49152;
    // seg 2: Wout [128][256]
    if (idx < 32768) {
        const int kp = idx >> 8, n = idx & 255;
        out[WP_WOUT + idx] = packbf(a.Wout[(size_t)(2*kp)*256 + n], a.Wout[(size_t)(2*kp+1)*256 + n]);
        return;
    }
    idx -= 32768;
    // seg 3: W1 [128][1024]
    if (idx < 131072) {
        const int kp = idx >> 10, n = idx & 1023;
        out[WP_W1 + idx] = packbf(a.W1[(size_t)(2*kp)*1024 + n], a.W1[(size_t)(2*kp+1)*1024 + n]);
        return;
    }
    idx -= 131072;
    // seg 4: W2 [512][256]
    if (idx < 131072) {
        const int kp = idx >> 8, n = idx & 255;
        out[WP_W2 + idx] = packbf(a.W2[(size_t)(2*kp)*256 + n], a.W2[(size_t)(2*kp+1)*256 + n]);
        return;
    }
    idx -= 131072;
    // seg 5: bias concat
    if (idx < 384)
        bcat[idx] = (idx < 256) ? a.boff[idx] : a.battn[idx - 256];
}

// ---------------- BF16 tensor-core GEMM ----------------
// C = act(A@B + bias) [+resid] [mask rows]; optional fp16 output.
// A fp32 [M,K]; Wp packed bf16-pairs [K/2][N]. N % 128 == 0, K % 32 == 0.
// CTA tile 64x128, K-tile 32, 4 warps.
#define A_STRB  80
#define A_STAGEB (64*A_STRB)
#define B_STRW  136
#define B_STAGEB (16*B_STRW*4)
#define GEMM_SMEM_BYTES (2*A_STAGEB + 2*B_STAGEB)

__global__ __launch_bounds__(128, 3) void gemm_bf(
    const float* __restrict__ A, const uint32_t* __restrict__ Wp,
    const float* __restrict__ bias, const float* __restrict__ resid,
    const uint8_t* __restrict__ mask, void* __restrict__ Cv,
    int M, int N, int K, int relu, int outhalf)
{
    extern __shared__ char smem[];
    char*     As = smem;
    uint32_t* Bs = (uint32_t*)(smem + 2*A_STAGEB);

    const int tid   = threadIdx.x;
    const int warpN = tid >> 5;
    const int lane  = tid & 31;
    const int gid   = lane >> 2;
    const int tig   = lane & 3;
    const int row0  = blockIdx.y * 64;
    const int col0  = blockIdx.x * 128;

    const int a_row  = tid >> 1;
    const int a_half = tid & 1;
    const bool avalid = (row0 + a_row) < M;
    const float* aptr = A + (size_t)(row0 + a_row) * K + a_half*16;

    const int lrow   = (lane & 7) + (((lane >> 3) & 1) << 3);
    const int lkhalf = (lane >> 4) & 1;
    const uint32_t a_sbase = (uint32_t)__cvta_generic_to_shared(As);

    float acc[4][4][4];
    #pragma unroll
    for (int i = 0; i < 4; i++)
        #pragma unroll
        for (int j = 0; j < 4; j++)
            #pragma unroll
            for (int r = 0; r < 4; r++) acc[i][j][r] = 0.f;

    const int nkt = K >> 5;
    const int KPW = N;
    float4 ra[4];

    auto fillB = [&](int p, int t) {
        uint32_t* bdst = Bs + p * (B_STAGEB/4);
        const uint32_t* gB = Wp + (size_t)(t*16) * KPW + col0;
        #pragma unroll
        for (int i = 0; i < 4; i++) {
            const int c = i*128 + tid;
            const int r = c >> 5;
            const int q = c & 31;
            cp_async16(&bdst[r*B_STRW + q*4], gB + (size_t)r*KPW + q*4);
        }
    };
    auto stsA = [&](int p) {
        uint32_t w[8];
        #pragma unroll
        for (int i = 0; i < 4; i++) {
            w[i*2+0] = packbf(ra[i].x, ra[i].y);
            w[i*2+1] = packbf(ra[i].z, ra[i].w);
        }
        char* dst = As + p*A_STAGEB + a_row*A_STRB + a_half*32;
        *(uint4*)(dst)      = make_uint4(w[0], w[1], w[2], w[3]);
        *(uint4*)(dst + 16) = make_uint4(w[4], w[5], w[6], w[7]);
    };

    #pragma unroll
    for (int i = 0; i < 4; i++)
        ra[i] = avalid ? *(const float4*)(aptr + i*4) : make_float4(0.f,0.f,0.f,0.f);
    fillB(0, 0);
    cp_commit();
    stsA(0);

    uint32_t af[2][4][4], bf[2][4][2];

    for (int t = 0; t < nkt; t++) {
        const int p = t & 1;
        cp_wait0();
        __syncthreads();

        const bool more = (t + 1) < nkt;
        if (more) {
            const int k0n = (t + 1) << 5;
            #pragma unroll
            for (int i = 0; i < 4; i++)
                ra[i] = avalid ? *(const float4*)(aptr + k0n + i*4)
                               : make_float4(0.f,0.f,0.f,0.f);
            fillB(p ^ 1, t + 1);
            cp_commit();
        }

        const uint32_t a_stage = a_sbase + (uint32_t)(p * A_STAGEB);
        const uint32_t* bb     = Bs + p * (B_STAGEB/4);
        const int cbase        = warpN * 32 + gid;

        #pragma unroll
        for (int mt = 0; mt < 4; mt++) {
            const uint32_t addr = a_stage
                + (uint32_t)((mt*16 + lrow)*A_STRB + lkhalf*16);
            asm volatile("ldmatrix.sync.aligned.m8n8.x4.shared.b16 {%0,%1,%2,%3}, [%4];"
                : "=r"(af[0][mt][0]), "=r"(af[0][mt][1]),
                  "=r"(af[0][mt][2]), "=r"(af[0][mt][3]) : "r"(addr));
        }
        #pragma unroll
        for (int nt = 0; nt < 4; nt++) {
            bf[0][nt][0] = bb[(tig    )*B_STRW + cbase + nt*8];
            bf[0][nt][1] = bb[(tig + 4)*B_STRW + cbase + nt*8];
        }

        #pragma unroll
        for (int ks = 0; ks < 2; ks++) {
            if (ks == 0) {
                #pragma unroll
                for (int mt = 0; mt < 4; mt++) {
                    const uint32_t addr = a_stage
                        + (uint32_t)((mt*16 + lrow)*A_STRB + 32 + lkhalf*16);
                    asm volatile("ldmatrix.sync.aligned.m8n8.x4.shared.b16 {%0,%1,%2,%3}, [%4];"
                        : "=r"(af[1][mt][0]), "=r"(af[1][mt][1]),
                          "=r"(af[1][mt][2]), "=r"(af[1][mt][3]) : "r"(addr));
                }
                #pragma unroll
                for (int nt = 0; nt < 4; nt++) {
                    bf[1][nt][0] = bb[(8 + tig    )*B_STRW + cbase + nt*8];
                    bf[1][nt][1] = bb[(8 + tig + 4)*B_STRW + cbase + nt*8];
                }
            }
            #pragma unroll
            for (int mt = 0; mt < 4; mt++)
                #pragma unroll
                for (int nt = 0; nt < 4; nt++)
                    mma_bf16(acc[mt][nt], af[ks][mt], bf[ks][nt]);
        }

        if (more) stsA(p ^ 1);
    }

    // ---- epilogue ----
    #pragma unroll
    for (int mt = 0; mt < 4; mt++) {
        #pragma unroll
        for (int half = 0; half < 2; half++) {
            const int r = row0 + mt*16 + gid + half*8;
            if (r >= M) continue;
            const float mz = (mask && mask[r]) ? 0.f : 1.f;
            #pragma unroll
            for (int nt = 0; nt < 4; nt++) {
                const int c = col0 + warpN*32 + nt*8 + 2*tig;
                float v0 = acc[mt][nt][half*2 + 0] + bias[c + 0];
                float v1 = acc[mt][nt][half*2 + 1] + bias[c + 1];
                if (relu) { v0 = fmaxf(v0, 0.f); v1 = fmaxf(v1, 0.f); }
                if (resid) {
                    const float* rp = resid + (size_t)r*N + c;
                    v0 += rp[0]; v1 += rp[1];
                }
                v0 *= mz; v1 *= mz;
                if (outhalf) {
                    __half2* hp = (__half2*)((__half*)Cv + (size_t)r*N + c);
                    *hp = __floats2half2_rn(v0, v1);
                } else {
                    *(float2*)((float*)Cv + (size_t)r*N + c) = make_float2(v0, v1);
                }
            }
        }
    }
}

// ---------------- fused loc + softmax + MS-deformable sampling (fp16 value) ----------------
// block = one (b,q), 128 threads; warp = 2 heads; lane = (head-sel, channel-pair).
__global__ __launch_bounds__(128) void sample_kernel(
    const __half* __restrict__ value, const float* __restrict__ offattn,
    const float* __restrict__ ref,
    float* __restrict__ out_loc, float* __restrict__ out)
{
    __shared__ float s_loc[256];
    __shared__ float s_attn[128];

    const int bq   = blockIdx.x;
    const int tid  = threadIdx.x;
    const int b    = bq >> 11;

    // loc = ref + off/normalizer  (off = cols [0,256) of offattn)
    #pragma unroll
    for (int i = 0; i < 2; i++) {
        const int j = tid + i*128;
        const int c = j & 1;
        const int l = (j >> 3) & 3;
        const float nd[4] = {100.f, 50.f, 25.f, 13.f};
        const float v = ref[((size_t)bq*4 + l)*2 + c]
                      + offattn[(size_t)bq*384 + j] / nd[l];
        s_loc[j] = v;
        out_loc[(size_t)bq*256 + j] = v;
    }
    // softmax over 16 points per head (logits = cols [256,384))
    {
        const float logit = offattn[(size_t)bq*384 + 256 + tid];
        float m = logit;
        #pragma unroll
        for (int o = 8; o; o >>= 1) m = fmaxf(m, __shfl_xor_sync(0xffffffffu, m, o, 16));
        const float e = __expf(logit - m);
        float s = e;
        #pragma unroll
        for (int o = 8; o; o >>= 1) s += __shfl_xor_sync(0xffffffffu, s, o, 16);
        s_attn[tid] = e / s;
    }
    __syncthreads();

    const int warp = tid >> 5;
    const int lane = tid & 31;
    const int h    = warp*2 + (lane >> 4);   // head
    const int cp   = lane & 15;              // channel pair

    const float* locp = s_loc  + h*32;
    const float* ap   = s_attn + h*16;

    constexpr int LH[4] = {100, 50, 25, 13};
    constexpr int LS[4] = {0, 10000, 12500, 13125};

    float a0 = 0.f, a1 = 0.f;
    #pragma unroll
    for (int l = 0; l < 4; l++) {
        const int Hh = LH[l], Ww = LH[l];
        const __half2* vb = (const __half2*)(value
            + ((size_t)b*LEN_IN_ + LS[l])*DIM_ + h*32) + cp;
        #pragma unroll
        for (int p = 0; p < 4; p++) {
            const float lx = locp[(l*4 + p)*2 + 0];
            const float ly = locp[(l*4 + p)*2 + 1];
            const float a  = ap[l*4 + p];
            const float x = lx * (float)Ww - 0.5f;
            const float y = ly * (float)Hh - 0.5f;
            const float x0f = floorf(x), y0f = floorf(y);
            const float wx = x - x0f, wy = y - y0f;
            const int x0 = (int)x0f, y0 = (int)y0f;
            const int x1 = x0 + 1,  y1 = y0 + 1;

            const float vx0 = (x0 >= 0 && x0 < Ww) ? 1.f : 0.f;
            const float vx1 = (x1 >= 0 && x1 < Ww) ? 1.f : 0.f;
            const float vy0 = (y0 >= 0 && y0 < Hh) ? 1.f : 0.f;
            const float vy1 = (y1 >= 0 && y1 < Hh) ? 1.f : 0.f;
            const int cx0 = min(max(x0, 0), Ww-1);
            const int cx1 = min(max(x1, 0), Ww-1);
            const int cy0 = min(max(y0, 0), Hh-1);
            const int cy1 = min(max(y1, 0), Hh-1);

            const float2 g00 = __half22float2(vb[(size_t)(cy0*Ww + cx0)*128]);
            const float2 g01 = __half22float2(vb[(size_t)(cy0*Ww + cx1)*128]);
            const float2 g10 = __half22float2(vb[(size_t)(cy1*Ww + cx0)*128]);
            const float2 g11 = __half22float2(vb[(size_t)(cy1*Ww + cx1)*128]);

            const float w00 = vx0*vy0*(1.f-wx)*(1.f-wy);
            const float w01 = vx1*vy0*wx*(1.f-wy);
            const float w10 = vx0*vy1*(1.f-wx)*wy;
            const float w11 = vx1*vy1*wx*wy;

            a0 += a * (g00.x*w00 + g01.x*w01 + g10.x*w10 + g11.x*w11);
            a1 += a * (g00.y*w00 + g01.y*w01 + g10.y*w10 + g11.y*w11);
        }
    }
    *(float2*)(out + (size_t)bq*256 + h*32 + cp*2) = make_float2(a0, a1);
}

// ---------------- launch ----------------
extern "C" void kernel_launch(void* const* d_in, const int* in_sizes, int n_in,
                              void* d_out, int out_size)
{
    const float*   input  = (const float*)d_in[0];
    const float*   pos    = (const float*)d_in[1];
    const float*   refp   = (const float*)d_in[2];
    const float*   source = (const float*)d_in[3];
    const uint8_t* mask   = (const uint8_t*)d_in[6];
    const float*   ln1_g  = (const float*)d_in[7];
    const float*   ln1_b  = (const float*)d_in[8];
    const float*   ln2_g  = (const float*)d_in[9];
    const float*   ln2_b  = (const float*)d_in[10];
    const float*   Wv     = (const float*)d_in[11];
    const float*   bv     = (const float*)d_in[12];
    const float*   Woff   = (const float*)d_in[13];
    const float*   boff   = (const float*)d_in[14];
    const float*   Wattn  = (const float*)d_in[15];
    const float*   battn  = (const float*)d_in[16];
    const float*   Wout   = (const float*)d_in[17];
    const float*   bout   = (const float*)d_in[18];
    const float*   W1     = (const float*)d_in[19];
    const float*   b1     = (const float*)d_in[20];
    const float*   W2     = (const float*)d_in[21];
    const float*   b2     = (const float*)d_in[22];

    float* out_x   = (float*)d_out;
    float* out_loc = (float*)d_out + (size_t)BQ*DIM_;

    float *qp, *offattn, *attnout, *xb, *yb, *ffn, *bcat;
    __half* valh;
    uint32_t* wp;
    cudaGetSymbolAddress((void**)&qp,      g_qp);
    cudaGetSymbolAddress((void**)&valh,    g_valh);
    cudaGetSymbolAddress((void**)&offattn, g_offattn);
    cudaGetSymbolAddress((void**)&attnout, g_attnout);
    cudaGetSymbolAddress((void**)&xb,      g_x);
    cudaGetSymbolAddress((void**)&yb,      g_y);
    cudaGetSymbolAddress((void**)&ffn,     g_ffn);
    cudaGetSymbolAddress((void**)&wp,      g_wp);
    cudaGetSymbolAddress((void**)&bcat,    g_bcat);

    cudaFuncSetAttribute(gemm_bf, cudaFuncAttributeMaxDynamicSharedMemorySize,
                         GEMM_SMEM_BYTES);

    // 0) pack all weights + bias concat (one launch)
    {
        WPackArgs a{Wv, Woff, Wattn, Wout, W1, W2, boff, battn};
        wconv_all<<<(376832 + 384 + 255)/256, 256>>>(a, wp, bcat);
    }

    // 1) qp = LN1(input) + pos
    ln_kernel<<<BQ, 256>>>(input, ln1_g, ln1_b, pos, qp);

    // 2) value = mask-zero(source @ Wv + bv) -> fp16
    {
        dim3 grid(DIM_/128, (MV + 63)/64);
        gemm_bf<<<grid, 128, GEMM_SMEM_BYTES>>>(source, wp + WP_WV, bv, nullptr, mask,
                                                valh, MV, DIM_, DIM_, 0, 1);
    }
    // 3) [offsets | attn logits] = qp @ [Woff|Wattn] + [boff|battn]
    {
        dim3 grid(384/128, BQ/64);
        gemm_bf<<<grid, 128, GEMM_SMEM_BYTES>>>(qp, wp + WP_PROJ, bcat, nullptr, nullptr,
                                                offattn, BQ, 384, DIM_, 0, 0);
    }
    // 4) fused loc + softmax + deformable sampling
    sample_kernel<<<BQ, 128>>>(valh, offattn, refp, out_loc, attnout);

    // 5) x = input + attnout @ Wout + bout
    {
        dim3 grid(DIM_/128, BQ/64);
        gemm_bf<<<grid, 128, GEMM_SMEM_BYTES>>>(attnout, wp + WP_WOUT, bout, input, nullptr,
                                                xb, BQ, DIM_, DIM_, 0, 0);
    }
    // 6) y = LN2(x)
    ln_kernel<<<BQ, 256>>>(xb, ln2_g, ln2_b, nullptr, yb);

    // 7) ffn = relu(y @ W1 + b1)
    {
        dim3 grid(DFF/128, BQ/64);
        gemm_bf<<<grid, 128, GEMM_SMEM_BYTES>>>(yb, wp + WP_W1, b1, nullptr, nullptr,
                                                ffn, BQ, DFF, DIM_, 1, 0);
    }
    // 8) out_x = x + ffn @ W2 + b2
    {
        dim3 grid(DIM_/128, BQ/64);
        gemm_bf<<<grid, 128, GEMM_SMEM_BYTES>>>(ffn, wp + WP_W2, b2, xb, nullptr,
                                                out_x, BQ, DIM_, DFF, 0, 0);
    }
}

// round 10
// speedup vs baseline: 1.6939x; 1.0598x over previous
#include <cuda_runtime.h>
#include <cuda_bf16.h>
#include <cuda_fp16.h>
#include <cstdint>

#define B_      8
#define Q_      2048
#define DIM_    256
#define NH      8
#define HD      32
#define DFF     1024
#define LEN_IN_ 13294
#define BQ      (B_*Q_)
#define MV      (B_*LEN_IN_)

// ---------------- scratch ----------------
__device__ float    g_qp[BQ*DIM_];
__device__ __half   g_valh[MV*DIM_];       // fp16 value (54 MB, L2-resident)
__device__ float    g_offattn[BQ*384];     // [off(256) | attn logits(128)]
__device__ float    g_attnout[BQ*DIM_];
__device__ float    g_x[BQ*DIM_];
__device__ float    g_y[BQ*DIM_];
__device__ float    g_ffn[BQ*DFF];
__device__ uint32_t g_wp[376832];          // packed bf16x2 weights (fragment layout)
__device__ float    g_bcat[384];           // concat bias [boff | battn]

// packed-weight word offsets
#define WP_WV    0
#define WP_PROJ  32768
#define WP_WOUT  81920
#define WP_W1    114688
#define WP_W2    245760

// ---------------- LayerNorm (+ optional additive term) ----------------
__global__ __launch_bounds__(256) void ln_kernel(
    const float* __restrict__ x, const float* __restrict__ g,
    const float* __restrict__ b, const float* __restrict__ addend,
    float* __restrict__ out)
{
    __shared__ float sbuf[8];
    const int row = blockIdx.x;
    const int t = threadIdx.x;
    const float v = x[(size_t)row*DIM_ + t];

    float s = v;
    #pragma unroll
    for (int o = 16; o; o >>= 1) s += __shfl_xor_sync(0xffffffffu, s, o);
    if ((t & 31) == 0) sbuf[t >> 5] = s;
    __syncthreads();
    float mean = 0.f;
    #pragma unroll
    for (int i = 0; i < 8; i++) mean += sbuf[i];
    mean *= (1.f/256.f);

    const float d = v - mean;
    float s2 = d*d;
    #pragma unroll
    for (int o = 16; o; o >>= 1) s2 += __shfl_xor_sync(0xffffffffu, s2, o);
    __syncthreads();
    if ((t & 31) == 0) sbuf[t >> 5] = s2;
    __syncthreads();
    float var = 0.f;
    #pragma unroll
    for (int i = 0; i < 8; i++) var += sbuf[i];
    var *= (1.f/256.f);

    float r = d * rsqrtf(var + 1e-5f) * g[t] + b[t];
    if (addend) r += addend[(size_t)row*DIM_ + t];
    out[(size_t)row*DIM_ + t] = r;
}

// ---------------- helpers ----------------
__device__ __forceinline__ uint32_t packbf(float lo, float hi) {
    uint32_t d;
    asm("cvt.rn.bf16x2.f32 %0, %1, %2;" : "=r"(d) : "f"(hi), "f"(lo));
    return d;
}

__device__ __forceinline__ void mma_bf16(float c[4], const uint32_t a[4],
                                         uint32_t b0, uint32_t b1) {
    asm("mma.sync.aligned.m16n8k16.row.col.f32.bf16.bf16.f32 "
        "{%0,%1,%2,%3}, {%4,%5,%6,%7}, {%8,%9}, {%0,%1,%2,%3};"
        : "+f"(c[0]), "+f"(c[1]), "+f"(c[2]), "+f"(c[3])
        : "r"(a[0]), "r"(a[1]), "r"(a[2]), "r"(a[3]), "r"(b0), "r"(b1));
}

// ---------------- single-launch weight pack (fragment-direct layout) ----------------
// Word index within a weight segment:
//   idx = ((n8 * (K/32) + t) * 32 + lane) * 4 + j
//   lane: gid = lane>>2 (n within n8 block), tig = lane&3
//   word j holds bf16 pair for kp = t*16 + tig + j*4, n = n8*8 + gid
//   (j=0,1 -> ks0 regs; j=2,3 -> ks1 regs of m16n8k16 B fragment)
struct WPackArgs {
    const float *Wv, *Woff, *Wattn, *Wout, *W1, *W2, *boff, *battn;
};

__device__ __forceinline__ uint32_t frag_pack(const float* __restrict__ W,
                                              int N, int K32, int idx)
{
    const int blk  = idx >> 7;
    const int r    = idx & 127;
    const int lane = r >> 2;
    const int j    = r & 3;
    const int gid  = lane >> 2;
    const int tig  = lane & 3;
    const int n8   = blk / K32;
    const int t    = blk - n8 * K32;
    const int kp   = t*16 + tig + j*4;
    const int n    = n8*8 + gid;
    return packbf(W[(size_t)(2*kp)*N + n], W[(size_t)(2*kp+1)*N + n]);
}

__global__ __launch_bounds__(256) void wconv_all(WPackArgs a, uint32_t* __restrict__ out,
                                                 float* __restrict__ bcat)
{
    int idx = blockIdx.x * 256 + threadIdx.x;

    // seg 0: Wv  K=256,N=256  (32768 words)
    if (idx < 32768) { out[WP_WV + idx] = frag_pack(a.Wv, 256, 8, idx); return; }
    idx -= 32768;
    // seg 1: projcat K=256, N=384 (Woff 256 ++ Wattn 128)  (49152 words)
    if (idx < 49152) {
        const int blk  = idx >> 7;
        const int r    = idx & 127;
        const int lane = r >> 2;
        const int j    = r & 3;
        const int gid  = lane >> 2;
        const int tig  = lane & 3;
        const int n8   = blk >> 3;          // K32 = 8
        const int t    = blk & 7;
        const int kp   = t*16 + tig + j*4;
        const int n    = n8*8 + gid;
        float lo, hi;
        if (n < 256) { lo = a.Woff[(size_t)(2*kp)*256 + n];      hi = a.Woff[(size_t)(2*kp+1)*256 + n]; }
        else         { lo = a.Wattn[(size_t)(2*kp)*128 + n-256]; hi = a.Wattn[(size_t)(2*kp+1)*128 + n-256]; }
        out[WP_PROJ + idx] = packbf(lo, hi);
        return;
    }
    idx -= 49152;
    // seg 2: Wout K=256,N=256
    if (idx < 32768) { out[WP_WOUT + idx] = frag_pack(a.Wout, 256, 8, idx); return; }
    idx -= 32768;
    // seg 3: W1 K=256,N=1024
    if (idx < 131072) { out[WP_W1 + idx] = frag_pack(a.W1, 1024, 8, idx); return; }
    idx -= 131072;
    // seg 4: W2 K=1024,N=256
    if (idx < 131072) { out[WP_W2 + idx] = frag_pack(a.W2, 256, 32, idx); return; }
    idx -= 131072;
    // seg 5: bias concat
    if (idx < 384) bcat[idx] = (idx < 256) ? a.boff[idx] : a.battn[idx - 256];
}

// ---------------- BF16 tensor-core GEMM, B fragment-direct from GMEM ----------------
// C = act(A @ W + bias) [+resid] [mask rows]; optional fp16 output.
// A fp32 [M,K]; Wp packed fragment layout. CTA: 128 threads, tile 64 x (WNT*32).
// A double-buffered in smem (10 KB), B fragments LDG.128 straight to MMA.
#define A_STRB   80
#define A_STAGEB (64*A_STRB)

template<int WNT>
__global__ __launch_bounds__(128) void gemm_bf(
    const float* __restrict__ A, const uint32_t* __restrict__ Wp,
    const float* __restrict__ bias, const float* __restrict__ resid,
    const uint8_t* __restrict__ mask, void* __restrict__ Cv,
    int M, int N, int K, int relu, int outhalf)
{
    __shared__ char smem[2*A_STAGEB];

    const int tid   = threadIdx.x;
    const int warpN = tid >> 5;
    const int lane  = tid & 31;
    const int gid   = lane >> 2;
    const int tig   = lane & 3;
    const int row0  = blockIdx.y * 64;
    const int col0  = blockIdx.x * (WNT*32);
    const int K32   = K >> 5;
    const int nblk0 = (col0 >> 3) + warpN*WNT;

    const int a_row  = tid >> 1;
    const int a_half = tid & 1;
    const bool avalid = (row0 + a_row) < M;
    const float* aptr = A + (size_t)(row0 + a_row) * K + a_half*16;

    const int lrow   = (lane & 7) + (((lane >> 3) & 1) << 3);
    const int lkhalf = (lane >> 4) & 1;
    const uint32_t a_sbase = (uint32_t)__cvta_generic_to_shared(smem);

    float acc[4][WNT][4];
    #pragma unroll
    for (int i = 0; i < 4; i++)
        #pragma unroll
        for (int j = 0; j < WNT; j++)
            #pragma unroll
            for (int r = 0; r < 4; r++) acc[i][j][r] = 0.f;

    float4 ra[4];
    auto stsA = [&](int p) {
        uint32_t w[8];
        #pragma unroll
        for (int i = 0; i < 4; i++) {
            w[i*2+0] = packbf(ra[i].x, ra[i].y);
            w[i*2+1] = packbf(ra[i].z, ra[i].w);
        }
        char* dst = smem + p*A_STAGEB + a_row*A_STRB + a_half*32;
        *(uint4*)(dst)      = make_uint4(w[0], w[1], w[2], w[3]);
        *(uint4*)(dst + 16) = make_uint4(w[4], w[5], w[6], w[7]);
    };

    // prologue: A(0) -> regs -> smem stage 0
    #pragma unroll
    for (int i = 0; i < 4; i++)
        ra[i] = avalid ? *(const float4*)(aptr + i*4) : make_float4(0.f,0.f,0.f,0.f);
    stsA(0);

    for (int t = 0; t < K32; t++) {
        const int p = t & 1;
        __syncthreads();

        const bool more = (t + 1) < K32;
        if (more) {
            const int k0n = (t + 1) << 5;
            #pragma unroll
            for (int i = 0; i < 4; i++)
                ra[i] = avalid ? *(const float4*)(aptr + k0n + i*4)
                               : make_float4(0.f,0.f,0.f,0.f);
        }

        // B fragments: one LDG.128 per n8 block (L1/L2-resident weights)
        uint4 bq[WNT];
        #pragma unroll
        for (int nt = 0; nt < WNT; nt++)
            bq[nt] = *(const uint4*)(Wp + (((size_t)(nblk0 + nt)*K32 + t) << 7) + (lane << 2));

        const uint32_t a_stage = a_sbase + (uint32_t)(p * A_STAGEB);
        #pragma unroll
        for (int ks = 0; ks < 2; ks++) {
            uint32_t af[4][4];
            #pragma unroll
            for (int mt = 0; mt < 4; mt++) {
                const uint32_t addr = a_stage
                    + (uint32_t)((mt*16 + lrow)*A_STRB + ks*32 + lkhalf*16);
                asm volatile("ldmatrix.sync.aligned.m8n8.x4.shared.b16 {%0,%1,%2,%3}, [%4];"
                    : "=r"(af[mt][0]), "=r"(af[mt][1]),
                      "=r"(af[mt][2]), "=r"(af[mt][3]) : "r"(addr));
            }
            #pragma unroll
            for (int mt = 0; mt < 4; mt++)
                #pragma unroll
                for (int nt = 0; nt < WNT; nt++) {
                    if (ks == 0) mma_bf16(acc[mt][nt], af[mt], bq[nt].x, bq[nt].y);
                    else         mma_bf16(acc[mt][nt], af[mt], bq[nt].z, bq[nt].w);
                }
        }

        if (more) stsA(p ^ 1);
    }

    // ---- epilogue ----
    #pragma unroll
    for (int mt = 0; mt < 4; mt++) {
        #pragma unroll
        for (int half = 0; half < 2; half++) {
            const int r = row0 + mt*16 + gid + half*8;
            if (r >= M) continue;
            const float mz = (mask && mask[r]) ? 0.f : 1.f;
            #pragma unroll
            for (int nt = 0; nt < WNT; nt++) {
                const int c = col0 + warpN*WNT*8 + nt*8 + 2*tig;
                float v0 = acc[mt][nt][half*2 + 0] + bias[c + 0];
                float v1 = acc[mt][nt][half*2 + 1] + bias[c + 1];
                if (relu) { v0 = fmaxf(v0, 0.f); v1 = fmaxf(v1, 0.f); }
                if (resid) {
                    const float* rp = resid + (size_t)r*N + c;
                    v0 += rp[0]; v1 += rp[1];
                }
                v0 *= mz; v1 *= mz;
                if (outhalf) {
                    __half2* hp = (__half2*)((__half*)Cv + (size_t)r*N + c);
                    *hp = __floats2half2_rn(v0, v1);
                } else {
                    *(float2*)((float*)Cv + (size_t)r*N + c) = make_float2(v0, v1);
                }
            }
        }
    }
}

// ---------------- fused loc + softmax + MS-deformable sampling (fp16 value) ----------------
__global__ __launch_bounds__(128) void sample_kernel(
    const __half* __restrict__ value, const float* __restrict__ offattn,
    const float* __restrict__ ref,
    float* __restrict__ out_loc, float* __restrict__ out)
{
    __shared__ float s_loc[256];
    __shared__ float s_attn[128];

    const int bq   = blockIdx.x;
    const int tid  = threadIdx.x;
    const int b    = bq >> 11;

    #pragma unroll
    for (int i = 0; i < 2; i++) {
        const int j = tid + i*128;
        const int c = j & 1;
        const int l = (j >> 3) & 3;
        const float nd[4] = {100.f, 50.f, 25.f, 13.f};
        const float v = ref[((size_t)bq*4 + l)*2 + c]
                      + offattn[(size_t)bq*384 + j] / nd[l];
        s_loc[j] = v;
        out_loc[(size_t)bq*256 + j] = v;
    }
    {
        const float logit = offattn[(size_t)bq*384 + 256 + tid];
        float m = logit;
        #pragma unroll
        for (int o = 8; o; o >>= 1) m = fmaxf(m, __shfl_xor_sync(0xffffffffu, m, o, 16));
        const float e = __expf(logit - m);
        float s = e;
        #pragma unroll
        for (int o = 8; o; o >>= 1) s += __shfl_xor_sync(0xffffffffu, s, o, 16);
        s_attn[tid] = e / s;
    }
    __syncthreads();

    const int warp = tid >> 5;
    const int lane = tid & 31;
    const int h    = warp*2 + (lane >> 4);
    const int cp   = lane & 15;

    const float* locp = s_loc  + h*32;
    const float* ap   = s_attn + h*16;

    constexpr int LH[4] = {100, 50, 25, 13};
    constexpr int LS[4] = {0, 10000, 12500, 13125};

    float a0 = 0.f, a1 = 0.f;
    #pragma unroll
    for (int l = 0; l < 4; l++) {
        const int Hh = LH[l], Ww = LH[l];
        const __half2* vb = (const __half2*)(value
            + ((size_t)b*LEN_IN_ + LS[l])*DIM_ + h*32) + cp;
        #pragma unroll
        for (int p = 0; p < 4; p++) {
            const float lx = locp[(l*4 + p)*2 + 0];
            const float ly = locp[(l*4 + p)*2 + 1];
            const float a  = ap[l*4 + p];
            const float x = lx * (float)Ww - 0.5f;
            const float y = ly * (float)Hh - 0.5f;
            const float x0f = floorf(x), y0f = floorf(y);
            const float wx = x - x0f, wy = y - y0f;
            const int x0 = (int)x0f, y0 = (int)y0f;
            const int x1 = x0 + 1,  y1 = y0 + 1;

            const float vx0 = (x0 >= 0 && x0 < Ww) ? 1.f : 0.f;
            const float vx1 = (x1 >= 0 && x1 < Ww) ? 1.f : 0.f;
            const float vy0 = (y0 >= 0 && y0 < Hh) ? 1.f : 0.f;
            const float vy1 = (y1 >= 0 && y1 < Hh) ? 1.f : 0.f;
            const int cx0 = min(max(x0, 0), Ww-1);
            const int cx1 = min(max(x1, 0), Ww-1);
            const int cy0 = min(max(y0, 0), Hh-1);
            const int cy1 = min(max(y1, 0), Hh-1);

            const float2 g00 = __half22float2(vb[(size_t)(cy0*Ww + cx0)*128]);
            const float2 g01 = __half22float2(vb[(size_t)(cy0*Ww + cx1)*128]);
            const float2 g10 = __half22float2(vb[(size_t)(cy1*Ww + cx0)*128]);
            const float2 g11 = __half22float2(vb[(size_t)(cy1*Ww + cx1)*128]);

            const float w00 = vx0*vy0*(1.f-wx)*(1.f-wy);
            const float w01 = vx1*vy0*wx*(1.f-wy);
            const float w10 = vx0*vy1*(1.f-wx)*wy;
            const float w11 = vx1*vy1*wx*wy;

            a0 += a * (g00.x*w00 + g01.x*w01 + g10.x*w10 + g11.x*w11);
            a1 += a * (g00.y*w00 + g01.y*w01 + g10.y*w10 + g11.y*w11);
        }
    }
    *(float2*)(out + (size_t)bq*256 + h*32 + cp*2) = make_float2(a0, a1);
}

// ---------------- launch ----------------
extern "C" void kernel_launch(void* const* d_in, const int* in_sizes, int n_in,
                              void* d_out, int out_size)
{
    const float*   input  = (const float*)d_in[0];
    const float*   pos    = (const float*)d_in[1];
    const float*   refp   = (const float*)d_in[2];
    const float*   source = (const float*)d_in[3];
    const uint8_t* mask   = (const uint8_t*)d_in[6];
    const float*   ln1_g  = (const float*)d_in[7];
    const float*   ln1_b  = (const float*)d_in[8];
    const float*   ln2_g  = (const float*)d_in[9];
    const float*   ln2_b  = (const float*)d_in[10];
    const float*   Wv     = (const float*)d_in[11];
    const float*   bv     = (const float*)d_in[12];
    const float*   Woff   = (const float*)d_in[13];
    const float*   boff   = (const float*)d_in[14];
    const float*   Wattn  = (const float*)d_in[15];
    const float*   battn  = (const float*)d_in[16];
    const float*   Wout   = (const float*)d_in[17];
    const float*   bout   = (const float*)d_in[18];
    const float*   W1     = (const float*)d_in[19];
    const float*   b1     = (const float*)d_in[20];
    const float*   W2     = (const float*)d_in[21];
    const float*   b2     = (const float*)d_in[22];

    float* out_x   = (float*)d_out;
    float* out_loc = (float*)d_out + (size_t)BQ*DIM_;

    float *qp, *offattn, *attnout, *xb, *yb, *ffn, *bcat;
    __half* valh;
    uint32_t* wp;
    cudaGetSymbolAddress((void**)&qp,      g_qp);
    cudaGetSymbolAddress((void**)&valh,    g_valh);
    cudaGetSymbolAddress((void**)&offattn, g_offattn);
    cudaGetSymbolAddress((void**)&attnout, g_attnout);
    cudaGetSymbolAddress((void**)&xb,      g_x);
    cudaGetSymbolAddress((void**)&yb,      g_y);
    cudaGetSymbolAddress((void**)&ffn,     g_ffn);
    cudaGetSymbolAddress((void**)&wp,      g_wp);
    cudaGetSymbolAddress((void**)&bcat,    g_bcat);

    // 0) pack all weights into fragment-direct layout + bias concat
    {
        WPackArgs a{Wv, Woff, Wattn, Wout, W1, W2, boff, battn};
        wconv_all<<<(376832 + 384 + 255)/256, 256>>>(a, wp, bcat);
    }

    // 1) qp = LN1(input) + pos
    ln_kernel<<<BQ, 256>>>(input, ln1_g, ln1_b, pos, qp);

    // 2) value = mask-zero(source @ Wv + bv) -> fp16
    gemm_bf<8><<<dim3(1, (MV + 63)/64), 128>>>(source, wp + WP_WV, bv, nullptr, mask,
                                               valh, MV, DIM_, DIM_, 0, 1);

    // 3) [offsets | attn logits] = qp @ [Woff|Wattn] + [boff|battn]
    gemm_bf<4><<<dim3(3, BQ/64), 128>>>(qp, wp + WP_PROJ, bcat, nullptr, nullptr,
                                        offattn, BQ, 384, DIM_, 0, 0);

    // 4) fused loc + softmax + deformable sampling
    sample_kernel<<<BQ, 128>>>(valh, offattn, refp, out_loc, attnout);

    // 5) x = input + attnout @ Wout + bout
    gemm_bf<8><<<dim3(1, BQ/64), 128>>>(attnout, wp + WP_WOUT, bout, input, nullptr,
                                        xb, BQ, DIM_, DIM_, 0, 0);

    // 6) y = LN2(x)
    ln_kernel<<<BQ, 256>>>(xb, ln2_g, ln2_b, nullptr, yb);

    // 7) ffn = relu(y @ W1 + b1)
    gemm_bf<8><<<dim3(DFF/256, BQ/64), 128>>>(yb, wp + WP_W1, b1, nullptr, nullptr,
                                              ffn, BQ, DFF, DIM_, 1, 0);

    // 8) out_x = x + ffn @ W2 + b2
    gemm_bf<8><<<dim3(1, BQ/64), 128>>>(ffn, wp + WP_W2, b2, xb, nullptr,
                                        out_x, BQ, DIM_, DFF, 0, 0);
}

// round 11
// speedup vs baseline: 1.7918x; 1.0578x over previous
#include <cuda_runtime.h>
#include <cuda_bf16.h>
#include <cuda_fp16.h>
#include <cstdint>

#define B_      8
#define Q_      2048
#define DIM_    256
#define NH      8
#define HD      32
#define DFF     1024
#define LEN_IN_ 13294
#define BQ      (B_*Q_)
#define MV      (B_*LEN_IN_)

// ---------------- scratch ----------------
__device__ float    g_qp[BQ*DIM_];
__device__ __half   g_valh[MV*DIM_];       // fp16 value (54 MB, L2-resident)
__device__ float    g_offattn[BQ*384];     // [off(256) | attn logits(128)]
__device__ float    g_attnout[BQ*DIM_];
__device__ float    g_x[BQ*DIM_];
__device__ float    g_y[BQ*DIM_];
__device__ float    g_ffn[BQ*DFF];
__device__ uint32_t g_wp[376832];          // packed bf16x2 weights (fragment layout)
__device__ float    g_bcat[384];           // concat bias [boff | battn]

// packed-weight word offsets
#define WP_WV    0
#define WP_PROJ  32768
#define WP_WOUT  81920
#define WP_W1    114688
#define WP_W2    245760

// ---------------- LayerNorm (+ optional additive term) ----------------
__global__ __launch_bounds__(256) void ln_kernel(
    const float* __restrict__ x, const float* __restrict__ g,
    const float* __restrict__ b, const float* __restrict__ addend,
    float* __restrict__ out)
{
    __shared__ float sbuf[8];
    const int row = blockIdx.x;
    const int t = threadIdx.x;
    const float v = x[(size_t)row*DIM_ + t];

    float s = v;
    #pragma unroll
    for (int o = 16; o; o >>= 1) s += __shfl_xor_sync(0xffffffffu, s, o);
    if ((t & 31) == 0) sbuf[t >> 5] = s;
    __syncthreads();
    float mean = 0.f;
    #pragma unroll
    for (int i = 0; i < 8; i++) mean += sbuf[i];
    mean *= (1.f/256.f);

    const float d = v - mean;
    float s2 = d*d;
    #pragma unroll
    for (int o = 16; o; o >>= 1) s2 += __shfl_xor_sync(0xffffffffu, s2, o);
    __syncthreads();
    if ((t & 31) == 0) sbuf[t >> 5] = s2;
    __syncthreads();
    float var = 0.f;
    #pragma unroll
    for (int i = 0; i < 8; i++) var += sbuf[i];
    var *= (1.f/256.f);

    float r = d * rsqrtf(var + 1e-5f) * g[t] + b[t];
    if (addend) r += addend[(size_t)row*DIM_ + t];
    out[(size_t)row*DIM_ + t] = r;
}

// ---------------- helpers ----------------
__device__ __forceinline__ uint32_t packbf(float lo, float hi) {
    uint32_t d;
    asm("cvt.rn.bf16x2.f32 %0, %1, %2;" : "=r"(d) : "f"(hi), "f"(lo));
    return d;
}

__device__ __forceinline__ void mma_bf16(float c[4], const uint32_t a[4],
                                         uint32_t b0, uint32_t b1) {
    asm("mma.sync.aligned.m16n8k16.row.col.f32.bf16.bf16.f32 "
        "{%0,%1,%2,%3}, {%4,%5,%6,%7}, {%8,%9}, {%0,%1,%2,%3};"
        : "+f"(c[0]), "+f"(c[1]), "+f"(c[2]), "+f"(c[3])
        : "r"(a[0]), "r"(a[1]), "r"(a[2]), "r"(a[3]), "r"(b0), "r"(b1));
}

// ---------------- single-launch weight pack (fragment-direct layout) ----------------
// Word index within a weight segment:
//   idx = ((n8 * (K/32) + t) * 32 + lane) * 4 + j
//   word j holds bf16 pair for kp = t*16 + tig + j*4, n = n8*8 + gid
struct WPackArgs {
    const float *Wv, *Woff, *Wattn, *Wout, *W1, *W2, *boff, *battn;
};

__device__ __forceinline__ uint32_t frag_pack(const float* __restrict__ W,
                                              int N, int K32, int idx)
{
    const int blk  = idx >> 7;
    const int r    = idx & 127;
    const int lane = r >> 2;
    const int j    = r & 3;
    const int gid  = lane >> 2;
    const int tig  = lane & 3;
    const int n8   = blk / K32;
    const int t    = blk - n8 * K32;
    const int kp   = t*16 + tig + j*4;
    const int n    = n8*8 + gid;
    return packbf(W[(size_t)(2*kp)*N + n], W[(size_t)(2*kp+1)*N + n]);
}

__global__ __launch_bounds__(256) void wconv_all(WPackArgs a, uint32_t* __restrict__ out,
                                                 float* __restrict__ bcat)
{
    int idx = blockIdx.x * 256 + threadIdx.x;

    if (idx < 32768) { out[WP_WV + idx] = frag_pack(a.Wv, 256, 8, idx); return; }
    idx -= 32768;
    if (idx < 49152) {   // projcat K=256, N=384
        const int blk  = idx >> 7;
        const int r    = idx & 127;
        const int lane = r >> 2;
        const int j    = r & 3;
        const int gid  = lane >> 2;
        const int tig  = lane & 3;
        const int n8   = blk >> 3;
        const int t    = blk & 7;
        const int kp   = t*16 + tig + j*4;
        const int n    = n8*8 + gid;
        float lo, hi;
        if (n < 256) { lo = a.Woff[(size_t)(2*kp)*256 + n];      hi = a.Woff[(size_t)(2*kp+1)*256 + n]; }
        else         { lo = a.Wattn[(size_t)(2*kp)*128 + n-256]; hi = a.Wattn[(size_t)(2*kp+1)*128 + n-256]; }
        out[WP_PROJ + idx] = packbf(lo, hi);
        return;
    }
    idx -= 49152;
    if (idx < 32768) { out[WP_WOUT + idx] = frag_pack(a.Wout, 256, 8, idx); return; }
    idx -= 32768;
    if (idx < 131072) { out[WP_W1 + idx] = frag_pack(a.W1, 1024, 8, idx); return; }
    idx -= 131072;
    if (idx < 131072) { out[WP_W2 + idx] = frag_pack(a.W2, 256, 32, idx); return; }
    idx -= 131072;
    if (idx < 384) bcat[idx] = (idx < 256) ? a.boff[idx] : a.battn[idx - 256];
}

// ---------------- BF16 tensor-core GEMM, fully software-pipelined ----------------
// C = act(A @ W + bias) [+resid] [mask rows]; optional fp16 output.
// A fp32 [M,K]; Wp fragment layout. CTA: 128 threads, tile 64 x (WNT*32).
// A double-buffered in smem; B fragments register double-buffered (LDG for
// tile t+1 issued before tile t's MMA chain); all A frags LDSM'd up front.
#define A_STRB   80
#define A_STAGEB (64*A_STRB)

template<int WNT>
__global__ __launch_bounds__(128) void gemm_bf(
    const float* __restrict__ A, const uint32_t* __restrict__ Wp,
    const float* __restrict__ bias, const float* __restrict__ resid,
    const uint8_t* __restrict__ mask, void* __restrict__ Cv,
    int M, int N, int K, int relu, int outhalf)
{
    __shared__ char smem[2*A_STAGEB];

    const int tid   = threadIdx.x;
    const int warpN = tid >> 5;
    const int lane  = tid & 31;
    const int gid   = lane >> 2;
    const int tig   = lane & 3;
    const int row0  = blockIdx.y * 64;
    const int col0  = blockIdx.x * (WNT*32);
    const int K32   = K >> 5;
    const int nblk0 = (col0 >> 3) + warpN*WNT;

    const int a_row  = tid >> 1;
    const int a_half = tid & 1;
    const bool avalid = (row0 + a_row) < M;
    const float* aptr = A + (size_t)(row0 + a_row) * K + a_half*16;

    const int lrow   = (lane & 7) + (((lane >> 3) & 1) << 3);
    const int lkhalf = (lane >> 4) & 1;
    const uint32_t a_sbase = (uint32_t)__cvta_generic_to_shared(smem);

    float acc[4][WNT][4];
    #pragma unroll
    for (int i = 0; i < 4; i++)
        #pragma unroll
        for (int j = 0; j < WNT; j++)
            #pragma unroll
            for (int r = 0; r < 4; r++) acc[i][j][r] = 0.f;

    float4 ra[4];
    auto stsA = [&](int p) {
        uint32_t w[8];
        #pragma unroll
        for (int i = 0; i < 4; i++) {
            w[i*2+0] = packbf(ra[i].x, ra[i].y);
            w[i*2+1] = packbf(ra[i].z, ra[i].w);
        }
        char* dst = smem + p*A_STAGEB + a_row*A_STRB + a_half*32;
        *(uint4*)(dst)      = make_uint4(w[0], w[1], w[2], w[3]);
        *(uint4*)(dst + 16) = make_uint4(w[4], w[5], w[6], w[7]);
    };

    uint4 bqb[2][WNT];

    // ---- prologue: A(0) + B(0), stage 0 ----
    #pragma unroll
    for (int i = 0; i < 4; i++)
        ra[i] = avalid ? *(const float4*)(aptr + i*4) : make_float4(0.f,0.f,0.f,0.f);
    #pragma unroll
    for (int nt = 0; nt < WNT; nt++)
        bqb[0][nt] = *(const uint4*)(Wp + (((size_t)(nblk0 + nt)*K32) << 7) + (lane << 2));
    stsA(0);

    #pragma unroll 2
    for (int t = 0; t < K32; t++) {
        const int p = t & 1;
        __syncthreads();

        const bool more = (t + 1) < K32;
        if (more) {
            const int k0n = (t + 1) << 5;
            #pragma unroll
            for (int i = 0; i < 4; i++)
                ra[i] = avalid ? *(const float4*)(aptr + k0n + i*4)
                               : make_float4(0.f,0.f,0.f,0.f);
            #pragma unroll
            for (int nt = 0; nt < WNT; nt++)
                bqb[p ^ 1][nt] = *(const uint4*)(Wp
                    + (((size_t)(nblk0 + nt)*K32 + t + 1) << 7) + (lane << 2));
        }

        // ---- all A fragments up front (8 LDSM), then 32 MMAs ----
        const uint32_t a_stage = a_sbase + (uint32_t)(p * A_STAGEB);
        uint32_t af[2][4][4];
        #pragma unroll
        for (int ks = 0; ks < 2; ks++)
            #pragma unroll
            for (int mt = 0; mt < 4; mt++) {
                const uint32_t addr = a_stage
                    + (uint32_t)((mt*16 + lrow)*A_STRB + ks*32 + lkhalf*16);
                asm volatile("ldmatrix.sync.aligned.m8n8.x4.shared.b16 {%0,%1,%2,%3}, [%4];"
                    : "=r"(af[ks][mt][0]), "=r"(af[ks][mt][1]),
                      "=r"(af[ks][mt][2]), "=r"(af[ks][mt][3]) : "r"(addr));
            }
        #pragma unroll
        for (int ks = 0; ks < 2; ks++)
            #pragma unroll
            for (int mt = 0; mt < 4; mt++)
                #pragma unroll
                for (int nt = 0; nt < WNT; nt++) {
                    if (ks == 0) mma_bf16(acc[mt][nt], af[0][mt], bqb[p][nt].x, bqb[p][nt].y);
                    else         mma_bf16(acc[mt][nt], af[1][mt], bqb[p][nt].z, bqb[p][nt].w);
                }

        if (more) stsA(p ^ 1);
    }

    // ---- epilogue ----
    #pragma unroll
    for (int mt = 0; mt < 4; mt++) {
        #pragma unroll
        for (int half = 0; half < 2; half++) {
            const int r = row0 + mt*16 + gid + half*8;
            if (r >= M) continue;
            const float mz = (mask && mask[r]) ? 0.f : 1.f;
            #pragma unroll
            for (int nt = 0; nt < WNT; nt++) {
                const int c = col0 + warpN*WNT*8 + nt*8 + 2*tig;
                float v0 = acc[mt][nt][half*2 + 0] + bias[c + 0];
                float v1 = acc[mt][nt][half*2 + 1] + bias[c + 1];
                if (relu) { v0 = fmaxf(v0, 0.f); v1 = fmaxf(v1, 0.f); }
                if (resid) {
                    const float* rp = resid + (size_t)r*N + c;
                    v0 += rp[0]; v1 += rp[1];
                }
                v0 *= mz; v1 *= mz;
                if (outhalf) {
                    __half2* hp = (__half2*)((__half*)Cv + (size_t)r*N + c);
                    *hp = __floats2half2_rn(v0, v1);
                } else {
                    *(float2*)((float*)Cv + (size_t)r*N + c) = make_float2(v0, v1);
                }
            }
        }
    }
}

// ---------------- fused loc + softmax + MS-deformable sampling (fp16 value) ----------------
__global__ __launch_bounds__(128) void sample_kernel(
    const __half* __restrict__ value, const float* __restrict__ offattn,
    const float* __restrict__ ref,
    float* __restrict__ out_loc, float* __restrict__ out)
{
    __shared__ float s_loc[256];
    __shared__ float s_attn[128];

    const int bq   = blockIdx.x;
    const int tid  = threadIdx.x;
    const int b    = bq >> 11;

    #pragma unroll
    for (int i = 0; i < 2; i++) {
        const int j = tid + i*128;
        const int c = j & 1;
        const int l = (j >> 3) & 3;
        const float nd[4] = {100.f, 50.f, 25.f, 13.f};
        const float v = ref[((size_t)bq*4 + l)*2 + c]
                      + offattn[(size_t)bq*384 + j] / nd[l];
        s_loc[j] = v;
        out_loc[(size_t)bq*256 + j] = v;
    }
    {
        const float logit = offattn[(size_t)bq*384 + 256 + tid];
        float m = logit;
        #pragma unroll
        for (int o = 8; o; o >>= 1) m = fmaxf(m, __shfl_xor_sync(0xffffffffu, m, o, 16));
        const float e = __expf(logit - m);
        float s = e;
        #pragma unroll
        for (int o = 8; o; o >>= 1) s += __shfl_xor_sync(0xffffffffu, s, o, 16);
        s_attn[tid] = e / s;
    }
    __syncthreads();

    const int warp = tid >> 5;
    const int lane = tid & 31;
    const int h    = warp*2 + (lane >> 4);
    const int cp   = lane & 15;

    const float* locp = s_loc  + h*32;
    const float* ap   = s_attn + h*16;

    constexpr int LH[4] = {100, 50, 25, 13};
    constexpr int LS[4] = {0, 10000, 12500, 13125};

    float a0 = 0.f, a1 = 0.f;
    #pragma unroll
    for (int l = 0; l < 4; l++) {
        const int Hh = LH[l], Ww = LH[l];
        const __half2* vb = (const __half2*)(value
            + ((size_t)b*LEN_IN_ + LS[l])*DIM_ + h*32) + cp;
        #pragma unroll
        for (int p = 0; p < 4; p++) {
            const float lx = locp[(l*4 + p)*2 + 0];
            const float ly = locp[(l*4 + p)*2 + 1];
            const float a  = ap[l*4 + p];
            const float x = lx * (float)Ww - 0.5f;
            const float y = ly * (float)Hh - 0.5f;
            const float x0f = floorf(x), y0f = floorf(y);
            const float wx = x - x0f, wy = y - y0f;
            const int x0 = (int)x0f, y0 = (int)y0f;
            const int x1 = x0 + 1,  y1 = y0 + 1;

            const float vx0 = (x0 >= 0 && x0 < Ww) ? 1.f : 0.f;
            const float vx1 = (x1 >= 0 && x1 < Ww) ? 1.f : 0.f;
            const float vy0 = (y0 >= 0 && y0 < Hh) ? 1.f : 0.f;
            const float vy1 = (y1 >= 0 && y1 < Hh) ? 1.f : 0.f;
            const int cx0 = min(max(x0, 0), Ww-1);
            const int cx1 = min(max(x1, 0), Ww-1);
            const int cy0 = min(max(y0, 0), Hh-1);
            const int cy1 = min(max(y1, 0), Hh-1);

            const float2 g00 = __half22float2(vb[(size_t)(cy0*Ww + cx0)*128]);
            const float2 g01 = __half22float2(vb[(size_t)(cy0*Ww + cx1)*128]);
            const float2 g10 = __half22float2(vb[(size_t)(cy1*Ww + cx0)*128]);
            const float2 g11 = __half22float2(vb[(size_t)(cy1*Ww + cx1)*128]);

            const float w00 = vx0*vy0*(1.f-wx)*(1.f-wy);
            const float w01 = vx1*vy0*wx*(1.f-wy);
            const float w10 = vx0*vy1*(1.f-wx)*wy;
            const float w11 = vx1*vy1*wx*wy;

            a0 += a * (g00.x*w00 + g01.x*w01 + g10.x*w10 + g11.x*w11);
            a1 += a * (g00.y*w00 + g01.y*w01 + g10.y*w10 + g11.y*w11);
        }
    }
    *(float2*)(out + (size_t)bq*256 + h*32 + cp*2) = make_float2(a0, a1);
}

// ---------------- launch ----------------
extern "C" void kernel_launch(void* const* d_in, const int* in_sizes, int n_in,
                              void* d_out, int out_size)
{
    const float*   input  = (const float*)d_in[0];
    const float*   pos    = (const float*)d_in[1];
    const float*   refp   = (const float*)d_in[2];
    const float*   source = (const float*)d_in[3];
    const uint8_t* mask   = (const uint8_t*)d_in[6];
    const float*   ln1_g  = (const float*)d_in[7];
    const float*   ln1_b  = (const float*)d_in[8];
    const float*   ln2_g  = (const float*)d_in[9];
    const float*   ln2_b  = (const float*)d_in[10];
    const float*   Wv     = (const float*)d_in[11];
    const float*   bv     = (const float*)d_in[12];
    const float*   Woff   = (const float*)d_in[13];
    const float*   boff   = (const float*)d_in[14];
    const float*   Wattn  = (const float*)d_in[15];
    const float*   battn  = (const float*)d_in[16];
    const float*   Wout   = (const float*)d_in[17];
    const float*   bout   = (const float*)d_in[18];
    const float*   W1     = (const float*)d_in[19];
    const float*   b1     = (const float*)d_in[20];
    const float*   W2     = (const float*)d_in[21];
    const float*   b2     = (const float*)d_in[22];

    float* out_x   = (float*)d_out;
    float* out_loc = (float*)d_out + (size_t)BQ*DIM_;

    float *qp, *offattn, *attnout, *xb, *yb, *ffn, *bcat;
    __half* valh;
    uint32_t* wp;
    cudaGetSymbolAddress((void**)&qp,      g_qp);
    cudaGetSymbolAddress((void**)&valh,    g_valh);
    cudaGetSymbolAddress((void**)&offattn, g_offattn);
    cudaGetSymbolAddress((void**)&attnout, g_attnout);
    cudaGetSymbolAddress((void**)&xb,      g_x);
    cudaGetSymbolAddress((void**)&yb,      g_y);
    cudaGetSymbolAddress((void**)&ffn,     g_ffn);
    cudaGetSymbolAddress((void**)&wp,      g_wp);
    cudaGetSymbolAddress((void**)&bcat,    g_bcat);

    // 0) pack all weights into fragment-direct layout + bias concat
    {
        WPackArgs a{Wv, Woff, Wattn, Wout, W1, W2, boff, battn};
        wconv_all<<<(376832 + 384 + 255)/256, 256>>>(a, wp, bcat);
    }

    // 1) qp = LN1(input) + pos
    ln_kernel<<<BQ, 256>>>(input, ln1_g, ln1_b, pos, qp);

    // 2) value = mask-zero(source @ Wv + bv) -> fp16
    gemm_bf<4><<<dim3(2, (MV + 63)/64), 128>>>(source, wp + WP_WV, bv, nullptr, mask,
                                               valh, MV, DIM_, DIM_, 0, 1);

    // 3) [offsets | attn logits] = qp @ [Woff|Wattn] + [boff|battn]
    gemm_bf<4><<<dim3(3, BQ/64), 128>>>(qp, wp + WP_PROJ, bcat, nullptr, nullptr,
                                        offattn, BQ, 384, DIM_, 0, 0);

    // 4) fused loc + softmax + deformable sampling
    sample_kernel<<<BQ, 128>>>(valh, offattn, refp, out_loc, attnout);

    // 5) x = input + attnout @ Wout + bout
    gemm_bf<4><<<dim3(2, BQ/64), 128>>>(attnout, wp + WP_WOUT, bout, input, nullptr,
                                        xb, BQ, DIM_, DIM_, 0, 0);

    // 6) y = LN2(x)
    ln_kernel<<<BQ, 256>>>(xb, ln2_g, ln2_b, nullptr, yb);

    // 7) ffn = relu(y @ W1 + b1)
    gemm_bf<4><<<dim3(DFF/128, BQ/64), 128>>>(yb, wp + WP_W1, b1, nullptr, nullptr,
                                              ffn, BQ, DFF, DIM_, 1, 0);

    // 8) out_x = x + ffn @ W2 + b2
    gemm_bf<4><<<dim3(2, BQ/64), 128>>>(ffn, wp + WP_W2, b2, xb, nullptr,
                                        out_x, BQ, DIM_, DFF, 0, 0);
}